// round 6
// baseline (speedup 1.0000x reference)
#include <cuda_runtime.h>
#include <math.h>
#include <stdint.h>

#define LSEQ 1024
#define CEMB 1024
#define KD   1024
#define BB   8
#define NH   16
#define DH   64
#define NGRP 32

// ---------------- static scratch (device globals; no allocation) -------------
__device__ float    g_x  [(size_t)BB * CEMB * LSEQ];          // natural layout
__device__ float    g_h  [(size_t)BB * CEMB * LSEQ];          // l perm PG, tf32
__device__ float    g_qkv[(size_t)BB * 3 * CEMB * LSEQ];      // l perm PK, tf32
__device__ float    g_ao [(size_t)BB * CEMB * LSEQ];          // l perm PG, tf32
__device__ uint32_t g_wq [(size_t)6 * 3 * CEMB * CEMB];       // k perm PK, tf32 bits
__device__ uint32_t g_wp [(size_t)6 * CEMB * CEMB];           // k perm PK, tf32 bits

// PK (within 8):  stored = (k&~7) | ((k&3)<<1) | ((k>>2)&1)   pairs (k, k+4) adjacent
// PG (within 32): stored = (l&~31)| ((l&7)<<2) | ((l>>3)&3)   lane-g quads adjacent

// ---------------- helpers ----------------------------------------------------
__device__ __forceinline__ uint32_t f2tf(float f) {
    uint32_t u;
    asm("cvt.rna.tf32.f32 %0, %1;" : "=r"(u) : "f"(f));
    return u;
}

__device__ __forceinline__ void mma_tf32(float (&c)[4],
                                         uint32_t a0, uint32_t a1, uint32_t a2, uint32_t a3,
                                         uint32_t b0, uint32_t b1) {
    asm volatile(
        "mma.sync.aligned.m16n8k8.row.col.f32.tf32.tf32.f32 "
        "{%0,%1,%2,%3},{%4,%5,%6,%7},{%8,%9},{%0,%1,%2,%3};"
        : "+f"(c[0]), "+f"(c[1]), "+f"(c[2]), "+f"(c[3])
        : "r"(a0), "r"(a1), "r"(a2), "r"(a3), "r"(b0), "r"(b1));
}

__device__ __forceinline__ void cpa16(uint32_t dst, const void* src) {
    asm volatile("cp.async.cg.shared.global [%0], [%1], 16;" :: "r"(dst), "l"(src));
}
__device__ __forceinline__ void cpa_commit() {
    asm volatile("cp.async.commit_group;" ::);
}
template <int N>
__device__ __forceinline__ void cpa_wait() {
    asm volatile("cp.async.wait_group %0;" :: "n"(N));
}

// ---------------- weight pre-round + k-perm PK -------------------------------
__global__ void round_perm_w(const float* __restrict__ in, uint32_t* __restrict__ out, int n) {
    for (int i = blockIdx.x * 256 + threadIdx.x; i < n; i += gridDim.x * 256) {
        int k = i & (KD - 1);
        int kp = (k & ~7) | ((k & 3) << 1) | ((k >> 2) & 1);
        out[(i & ~(KD - 1)) | kp] = f2tf(in[i]);
    }
}

// ---------------- init projection (x natural) --------------------------------
__global__ void init_gemm(const float* __restrict__ speech, const float* __restrict__ W,
                          const float* __restrict__ bias, float* __restrict__ x) {
    __shared__ float Ws[16][80];
    __shared__ float Bs[16];
    int l  = blockIdx.x * 128 + threadIdx.x;
    int o0 = blockIdx.y * 16;
    int b  = blockIdx.z;
    for (int i = threadIdx.x; i < 16 * 80; i += 128)
        Ws[i / 80][i % 80] = W[(size_t)(o0 + i / 80) * 80 + (i % 80)];
    if (threadIdx.x < 16) Bs[threadIdx.x] = bias[o0 + threadIdx.x];
    __syncthreads();

    float acc[16];
    #pragma unroll
    for (int i = 0; i < 16; i++) acc[i] = Bs[i];
    const float* sp = speech + (size_t)b * 80 * LSEQ + l;
    for (int c = 0; c < 80; c++) {
        float sv = sp[(size_t)c * LSEQ];
        #pragma unroll
        for (int i = 0; i < 16; i++) acc[i] += Ws[i][c] * sv;
    }
    float* xp = x + ((size_t)b * CEMB + o0) * LSEQ + l;
    #pragma unroll
    for (int i = 0; i < 16; i++) xp[(size_t)i * LSEQ] = acc[i];
}

// ---------------- GroupNorm: x natural -> h (tf32, l-perm PG) ----------------
__global__ void group_norm_k(const float* __restrict__ x, const float* __restrict__ w,
                             const float* __restrict__ bb, float* __restrict__ h) {
    int bg = blockIdx.x;
    int b = bg >> 5, g = bg & 31;
    const float* xp = x + ((size_t)b * CEMB + g * 32) * LSEQ;
    float s = 0.f, ss = 0.f;
    for (int i = threadIdx.x; i < 32 * LSEQ; i += 256) {
        float v = xp[i];
        s += v; ss += v * v;
    }
    #pragma unroll
    for (int o = 16; o; o >>= 1) {
        s  += __shfl_down_sync(0xffffffffu, s,  o);
        ss += __shfl_down_sync(0xffffffffu, ss, o);
    }
    __shared__ float shs[8], shss[8];
    __shared__ float smean, srstd;
    int wid = threadIdx.x >> 5, lane = threadIdx.x & 31;
    if (!lane) { shs[wid] = s; shss[wid] = ss; }
    __syncthreads();
    if (threadIdx.x == 0) {
        float S = 0.f, SS = 0.f;
        #pragma unroll
        for (int i = 0; i < 8; i++) { S += shs[i]; SS += shss[i]; }
        float mean = S / 32768.f;
        float var  = SS / 32768.f - mean * mean;
        smean = mean;
        srstd = rsqrtf(var + 1e-5f);
    }
    __syncthreads();
    float mean = smean, rstd = srstd;
    float* hp = h + ((size_t)b * CEMB + g * 32) * LSEQ;
    for (int i = threadIdx.x; i < 32 * LSEQ; i += 256) {
        int c = g * 32 + (i >> 10);
        int iw = (i & ~31) | ((i & 7) << 2) | ((i >> 3) & 3);   // PG on l (low bits)
        hp[iw] = __uint_as_float(f2tf((xp[i] - mean) * rstd * w[c] + bb[c]));
    }
}

// ---------------- tf32 MMA GEMM, vectorized fragment loads -------------------
// A smem [m 128][k 32 PK-stored, stride 40] -> LDS.64 frags
// B smem [k 32][n 128 PG-stored, stride 136] -> LDS.128 frags
// Composition of PG store + uint4 gather (lane g takes stored 4g+ni, comp ni
// -> mma ni) yields NATURAL n order: mma ni, n-index j  <->  l = wn*32+ni*8+j.
// 3-stage cp.async; tile 128x128, BK=32, 8 warps (2m x 4n).
#define GEMM_AS_W   5120
#define GEMM_BUF_W  (GEMM_AS_W + 4352)
#define GEMM_SMEM   (GEMM_BUF_W * 3 * 4)

template <bool QKVOUT>
__global__ __launch_bounds__(256, 2) void gemm_wx_mma(
    const uint32_t* __restrict__ W, const float* __restrict__ bias,
    const float* __restrict__ X, const float* __restrict__ res,
    float* __restrict__ Y, int O)
{
    extern __shared__ uint32_t smbuf[];
    int tid = threadIdx.x, lane = tid & 31, warp = tid >> 5;
    int g = lane >> 2, tg = lane & 3;
    int wm = warp >> 2, wn = warp & 3;
    int b = blockIdx.z, o0 = blockIdx.y << 7, l0 = blockIdx.x << 7;
    const uint32_t* Wp = W + (size_t)o0 * KD;
    const float* Xp = X + (size_t)b * KD * LSEQ + l0;
    uint32_t sb = (uint32_t)__cvta_generic_to_shared(smbuf);

    auto prefetch = [&](int kc, int bufi) {
        uint32_t base = sb + (uint32_t)bufi * (GEMM_BUF_W * 4u);
        int k0 = kc << 5;
        #pragma unroll
        for (int j = 0; j < 4; j++) {
            int idx = tid + (j << 8);
            int r = idx >> 3, c = (idx & 7) << 2;
            cpa16(base + (uint32_t)(r * 40 + c) * 4u, Wp + (size_t)r * KD + k0 + c);
        }
        #pragma unroll
        for (int j = 0; j < 4; j++) {
            int idx = tid + (j << 8);
            int r2 = idx >> 5, c2 = (idx & 31) << 2;
            cpa16(base + (uint32_t)(GEMM_AS_W + r2 * 136 + c2) * 4u,
                  Xp + (size_t)(k0 + r2) * LSEQ + c2);
        }
        cpa_commit();
    };

    float acc[4][4][4] = {};
    prefetch(0, 0);
    prefetch(1, 1);
    int use = 0, pre = 2;

    for (int kc = 0; kc < 32; kc++) {
        if (kc < 30) cpa_wait<1>(); else cpa_wait<0>();
        __syncthreads();
        if (kc < 30) prefetch(kc + 2, pre);

        const uint32_t* As = smbuf + use * GEMM_BUF_W;
        const uint32_t* Bs = As + GEMM_AS_W;
        #pragma unroll
        for (int ks = 0; ks < 4; ks++) {
            int kk = ks << 3;
            uint2 aA[4], aB[4];
            #pragma unroll
            for (int mi = 0; mi < 4; mi++) {
                int row = wm * 64 + mi * 16 + g;
                aA[mi] = *(const uint2*)&As[row * 40 + kk + 2 * tg];        // (a0,a2)
                aB[mi] = *(const uint2*)&As[(row + 8) * 40 + kk + 2 * tg];  // (a1,a3)
            }
            uint4 b0 = *(const uint4*)&Bs[(kk + tg) * 136 + wn * 32 + (g << 2)];
            uint4 b1 = *(const uint4*)&Bs[(kk + tg + 4) * 136 + wn * 32 + (g << 2)];
            uint32_t bb0[4] = {b0.x, b0.y, b0.z, b0.w};
            uint32_t bb1[4] = {b1.x, b1.y, b1.z, b1.w};
            #pragma unroll
            for (int mi = 0; mi < 4; mi++)
                #pragma unroll
                for (int ni = 0; ni < 4; ni++)
                    mma_tf32(acc[mi][ni], aA[mi].x, aB[mi].x, aA[mi].y, aB[mi].y,
                             bb0[ni], bb1[ni]);
        }
        use = (use == 2) ? 0 : use + 1;
        pre = (pre == 2) ? 0 : pre + 1;
    }

    // epilogue: n order is NATURAL -> l = wn*32 + ni*8 + 2*tg (+1)
    #pragma unroll
    for (int mi = 0; mi < 4; mi++) {
        #pragma unroll
        for (int rr = 0; rr < 2; rr++) {
            int o = o0 + wm * 64 + mi * 16 + g + rr * 8;
            float bsv = bias[o];
            size_t rowoff = ((size_t)b * O + o) * LSEQ + l0;
            #pragma unroll
            for (int ni = 0; ni < 4; ni++) {
                int la = wn * 32 + ni * 8 + (tg << 1);      // even; la+1 same 8-block
                float v0 = acc[mi][ni][rr * 2]     + bsv;
                float v1 = acc[mi][ni][rr * 2 + 1] + bsv;
                if (QKVOUT) {
                    // store PK-permuted on l (for flash), tf32-rounded
                    int p0 = (la & ~7) | ((la & 3) << 1) | ((la >> 2) & 1);
                    int l1i = la + 1;
                    int p1 = (l1i & ~7) | ((l1i & 3) << 1) | ((l1i >> 2) & 1);
                    Y[rowoff + p0] = __uint_as_float(f2tf(v0));
                    Y[rowoff + p1] = __uint_as_float(f2tf(v1));
                } else {
                    float2 rv = *(const float2*)(res + rowoff + la);
                    *(float2*)(Y + rowoff + la) = make_float2(v0 + rv.x, v1 + rv.y);
                }
            }
        }
    }
}

// ---------------- fused flash attention (qkv is PK-l-permuted) ---------------
#define FA_QS 0                        // [c 64][t 128+8]   stride 136
#define FA_KS 8704                     // [c 64][s 128+8]   stride 136
#define FA_VS 17408                    // [c 64][s 128+8]   stride 136
#define FA_PS 26112                    // [t 128][s 128+8]  stride 136
#define FA_SMEM ((26112 + 128 * 136) * 4)

__global__ __launch_bounds__(256, 1) void flash_attn(
    const float* __restrict__ qkv, float* __restrict__ ao)
{
    extern __shared__ uint32_t sm[];
    uint32_t* Qs = sm + FA_QS;
    uint32_t* Ks = sm + FA_KS;
    uint32_t* Vs = sm + FA_VS;
    uint32_t* Ps = sm + FA_PS;
    uint32_t fb = (uint32_t)__cvta_generic_to_shared(sm);

    int tid = threadIdx.x, lane = tid & 31, warp = tid >> 5;
    int g = lane >> 2, tg = lane & 3;
    int tw = warp << 4;
    int bh = blockIdx.y, b = bh >> 4, hh = bh & 15;
    int t0 = blockIdx.x << 7;
    const float* Q  = qkv + ((size_t)b * 3 * CEMB + hh * 192) * LSEQ;
    const float* Kp = Q + (size_t)DH * LSEQ;
    const float* Vp = Q + (size_t)(2 * DH) * LSEQ;

    #pragma unroll
    for (int j = 0; j < 8; j++) {
        int idx = tid + (j << 8);
        int r = idx >> 5, c4 = (idx & 31) << 2;
        cpa16(fb + (uint32_t)(FA_QS + r * 136 + c4) * 4u, Q  + (size_t)r * LSEQ + t0 + c4);
        cpa16(fb + (uint32_t)(FA_KS + r * 136 + c4) * 4u, Kp + (size_t)r * LSEQ + c4);
        cpa16(fb + (uint32_t)(FA_VS + r * 136 + c4) * 4u, Vp + (size_t)r * LSEQ + c4);
    }
    cpa_commit();

    float accO[8][4] = {};
    float m0 = -1e30f, m1 = -1e30f, l0 = 0.f, l1 = 0.f;

    for (int s0 = 0; s0 < LSEQ; s0 += 128) {
        cpa_wait<0>();
        __syncthreads();

        // S[16t x 128s] per warp (Qs/Ks cols are PK-stored positions)
        float accS[16][4] = {};
        #pragma unroll
        for (int kk = 0; kk < 8; kk++) {
            const uint32_t* p = &Qs[(kk * 8 + tg) * 136 + tw + g];
            uint32_t a0 = p[0], a1 = p[8], a2 = p[4 * 136], a3 = p[4 * 136 + 8];
            #pragma unroll
            for (int ni = 0; ni < 16; ni++) {
                const uint32_t* q = &Ks[(kk * 8 + tg) * 136 + ni * 8 + g];
                mma_tf32(accS[ni], a0, a1, a2, a3, q[0], q[4 * 136]);
            }
        }

        // online softmax (order-invariant over permuted s)
        float tm0 = -1e30f, tm1 = -1e30f;
        #pragma unroll
        for (int ni = 0; ni < 16; ni++) {
            #pragma unroll
            for (int v = 0; v < 4; v++) accS[ni][v] *= 0.125f;
            tm0 = fmaxf(tm0, fmaxf(accS[ni][0], accS[ni][1]));
            tm1 = fmaxf(tm1, fmaxf(accS[ni][2], accS[ni][3]));
        }
        tm0 = fmaxf(tm0, __shfl_xor_sync(0xffffffffu, tm0, 1));
        tm0 = fmaxf(tm0, __shfl_xor_sync(0xffffffffu, tm0, 2));
        tm1 = fmaxf(tm1, __shfl_xor_sync(0xffffffffu, tm1, 1));
        tm1 = fmaxf(tm1, __shfl_xor_sync(0xffffffffu, tm1, 2));
        float nm0 = fmaxf(m0, tm0), nm1 = fmaxf(m1, tm1);
        float f0 = __expf(m0 - nm0), f1 = __expf(m1 - nm1);
        float ts0 = 0.f, ts1 = 0.f;
        #pragma unroll
        for (int ni = 0; ni < 16; ni++) {
            float p0 = __expf(accS[ni][0] - nm0);
            float p1 = __expf(accS[ni][1] - nm0);
            float p2 = __expf(accS[ni][2] - nm1);
            float p3 = __expf(accS[ni][3] - nm1);
            ts0 += p0 + p1; ts1 += p2 + p3;
            *(uint2*)&Ps[(tw + g) * 136 + ni * 8 + tg * 2]     = make_uint2(f2tf(p0), f2tf(p1));
            *(uint2*)&Ps[(tw + g + 8) * 136 + ni * 8 + tg * 2] = make_uint2(f2tf(p2), f2tf(p3));
        }
        ts0 += __shfl_xor_sync(0xffffffffu, ts0, 1);
        ts0 += __shfl_xor_sync(0xffffffffu, ts0, 2);
        ts1 += __shfl_xor_sync(0xffffffffu, ts1, 1);
        ts1 += __shfl_xor_sync(0xffffffffu, ts1, 2);
        l0 = l0 * f0 + ts0;
        l1 = l1 * f1 + ts1;
        m0 = nm0; m1 = nm1;
        #pragma unroll
        for (int ni = 0; ni < 8; ni++) {
            accO[ni][0] *= f0; accO[ni][1] *= f0;
            accO[ni][2] *= f1; accO[ni][3] *= f1;
        }
        __syncwarp();

        // O += P V^T : P cols and V cols are stored-s positions; A/B k-slots
        // pick the same physical s (stored 2tg -> slot tg, 2tg+1 -> slot tg+4)
        #pragma unroll
        for (int kk = 0; kk < 16; kk++) {
            uint2 a02 = *(const uint2*)&Ps[(tw + g) * 136 + kk * 8 + 2 * tg];
            uint2 a13 = *(const uint2*)&Ps[(tw + g + 8) * 136 + kk * 8 + 2 * tg];
            #pragma unroll
            for (int ni = 0; ni < 8; ni++) {
                uint2 bv = *(const uint2*)&Vs[(ni * 8 + g) * 136 + kk * 8 + 2 * tg];
                mma_tf32(accO[ni], a02.x, a13.x, a02.y, a13.y, bv.x, bv.y);
            }
        }
        __syncthreads();

        if (s0 + 128 < LSEQ) {
            int sn = s0 + 128;
            #pragma unroll
            for (int j = 0; j < 8; j++) {
                int idx = tid + (j << 8);
                int r = idx >> 5, c4 = (idx & 31) << 2;
                cpa16(fb + (uint32_t)(FA_KS + r * 136 + c4) * 4u, Kp + (size_t)r * LSEQ + sn + c4);
                cpa16(fb + (uint32_t)(FA_VS + r * 136 + c4) * 4u, Vp + (size_t)r * LSEQ + sn + c4);
            }
            cpa_commit();
        }
    }

    // epilogue: rows m are PK-stored t positions -> actual t; store ao PG(l)-perm
    float inv0 = 1.0f / l0, inv1 = 1.0f / l1;
    int d  = (g >> 1) + ((g & 1) << 2);     // PK inverse within 8-block
    int tA = t0 + tw + d;
    int tB = tA + 8;
    int colA = (tA & ~31) | ((tA & 7) << 2) | ((tA >> 3) & 3);
    int colB = (tB & ~31) | ((tB & 7) << 2) | ((tB >> 3) & 3);
    size_t base = ((size_t)b * CEMB + hh * 64) * LSEQ;
    #pragma unroll
    for (int ni = 0; ni < 8; ni++) {
        int c = ni * 8 + tg * 2;
        ao[base + (size_t)c * LSEQ + colA]       = __uint_as_float(f2tf(accO[ni][0] * inv0));
        ao[base + (size_t)(c + 1) * LSEQ + colA] = __uint_as_float(f2tf(accO[ni][1] * inv0));
        ao[base + (size_t)c * LSEQ + colB]       = __uint_as_float(f2tf(accO[ni][2] * inv1));
        ao[base + (size_t)(c + 1) * LSEQ + colB] = __uint_as_float(f2tf(accO[ni][3] * inv1));
    }
}

// ---------------- final: out[b,c] = x[b,c,0] --------------------------------
__global__ void take_col0(const float* __restrict__ x, float* __restrict__ out) {
    int i = blockIdx.x * 256 + threadIdx.x;
    out[i] = x[(size_t)i * LSEQ];
}

extern "C" void kernel_launch(void* const* d_in, const int* in_sizes, int n_in,
                              void* d_out, int out_size) {
    const float* speech = (const float*)d_in[0];
    const float* init_w = (const float*)d_in[1];
    const float* init_b = (const float*)d_in[2];
    const float* gn_w   = (const float*)d_in[3];
    const float* gn_b   = (const float*)d_in[4];
    const float* qkv_w  = (const float*)d_in[5];
    const float* qkv_b  = (const float*)d_in[6];
    const float* proj_w = (const float*)d_in[7];
    const float* proj_b = (const float*)d_in[8];

    float *x, *h, *qkv, *ao;
    uint32_t *wq, *wp;
    cudaGetSymbolAddress((void**)&x,   g_x);
    cudaGetSymbolAddress((void**)&h,   g_h);
    cudaGetSymbolAddress((void**)&qkv, g_qkv);
    cudaGetSymbolAddress((void**)&ao,  g_ao);
    cudaGetSymbolAddress((void**)&wq,  g_wq);
    cudaGetSymbolAddress((void**)&wp,  g_wp);

    cudaFuncSetAttribute(flash_attn, cudaFuncAttributeMaxDynamicSharedMemorySize, FA_SMEM);
    cudaFuncSetAttribute(gemm_wx_mma<true>,  cudaFuncAttributeMaxDynamicSharedMemorySize, GEMM_SMEM);
    cudaFuncSetAttribute(gemm_wx_mma<false>, cudaFuncAttributeMaxDynamicSharedMemorySize, GEMM_SMEM);

    round_perm_w<<<2048, 256>>>(qkv_w,  wq, 6 * 3 * CEMB * CEMB);
    round_perm_w<<<1024, 256>>>(proj_w, wp, 6 * CEMB * CEMB);

    init_gemm<<<dim3(LSEQ / 128, CEMB / 16, BB), 128>>>(speech, init_w, init_b, x);

    for (int i = 0; i < 6; i++) {
        group_norm_k<<<BB * NGRP, 256>>>(x, gn_w + (size_t)i * CEMB, gn_b + (size_t)i * CEMB, h);
        gemm_wx_mma<true><<<dim3(LSEQ / 128, 3 * CEMB / 128, BB), 256, GEMM_SMEM>>>(
            wq + (size_t)i * 3 * CEMB * CEMB, qkv_b + (size_t)i * 3 * CEMB,
            h, nullptr, qkv, 3 * CEMB);
        flash_attn<<<dim3(LSEQ / 128, BB * NH), 256, FA_SMEM>>>(qkv, ao);
        gemm_wx_mma<false><<<dim3(LSEQ / 128, CEMB / 128, BB), 256, GEMM_SMEM>>>(
            wp + (size_t)i * CEMB * CEMB, proj_b + (size_t)i * CEMB,
            ao, x, x, CEMB);
    }

    take_col0<<<32, 256>>>(x, (float*)d_out);
}

// round 8
// speedup vs baseline: 1.7656x; 1.7656x over previous
#include <cuda_runtime.h>
#include <cuda_fp16.h>
#include <math.h>
#include <stdint.h>

#define LSEQ 1024
#define CEMB 1024
#define KD   1024
#define KW   512      // k in half2 words
#define BB   8
#define NH   16
#define DH   64
#define NGRP 32

// ---------------- static scratch (device globals; no allocation) -------------
__device__ float    g_x   [(size_t)BB * CEMB * LSEQ];          // natural fp32
__device__ uint32_t g_h2  [(size_t)BB * KW * LSEQ];            // half2[c/2][l PG]
__device__ uint32_t g_qkv2[(size_t)BB * 1536 * LSEQ];          // per head: Q2[32][1024],K2[32][1024],V2[64][512]
__device__ uint32_t g_ao2 [(size_t)BB * KW * LSEQ];            // half2[c/2][t PG]
__device__ uint32_t g_wq2 [(size_t)6 * 3 * CEMB * KW];         // half2, PK word-perm
__device__ uint32_t g_wp2 [(size_t)6 * CEMB * KW];             // half2, PK word-perm

// PK (word idx within 8): stored = (kw&~7)|((kw&3)<<1)|((kw>>2)&1)  -> (tg, tg+4) adjacent
// PG (within 32): stored  = (l&~31)|((l&7)<<2)|((l>>3)&3)           -> lane-g quads adjacent

// ---------------- helpers ----------------------------------------------------
__device__ __forceinline__ void mma_f16(float (&c)[4],
                                        uint32_t a0, uint32_t a1, uint32_t a2, uint32_t a3,
                                        uint32_t b0, uint32_t b1) {
    asm volatile(
        "mma.sync.aligned.m16n8k16.row.col.f32.f16.f16.f32 "
        "{%0,%1,%2,%3},{%4,%5,%6,%7},{%8,%9},{%0,%1,%2,%3};"
        : "+f"(c[0]), "+f"(c[1]), "+f"(c[2]), "+f"(c[3])
        : "r"(a0), "r"(a1), "r"(a2), "r"(a3), "r"(b0), "r"(b1));
}

__device__ __forceinline__ uint32_t packh2(float a, float b) {
    __half2 h = __floats2half2_rn(a, b);
    return *(uint32_t*)&h;
}

__device__ __forceinline__ void cpa16(uint32_t dst, const void* src) {
    asm volatile("cp.async.cg.shared.global [%0], [%1], 16;" :: "r"(dst), "l"(src));
}
__device__ __forceinline__ void cpa_commit() {
    asm volatile("cp.async.commit_group;" ::);
}
template <int N>
__device__ __forceinline__ void cpa_wait() {
    asm volatile("cp.async.wait_group %0;" :: "n"(N));
}

// ---------------- weight pack: fp32 [o][k] -> half2 words [o][kw PK] ---------
__global__ void pack_w(const float* __restrict__ in, uint32_t* __restrict__ out, int nw) {
    for (int i = blockIdx.x * 256 + threadIdx.x; i < nw; i += gridDim.x * 256) {
        int o = i >> 9, kws = i & (KW - 1);
        int kw = (kws & ~7) | ((kws >> 1) & 3) | ((kws & 1) << 2);   // PK inverse
        const float* p = in + (size_t)o * KD + 2 * kw;
        out[i] = packh2(p[0], p[1]);
    }
}

// ---------------- init projection (x natural fp32) ---------------------------
__global__ void init_gemm(const float* __restrict__ speech, const float* __restrict__ W,
                          const float* __restrict__ bias, float* __restrict__ x) {
    __shared__ float Ws[16][80];
    __shared__ float Bs[16];
    int l  = blockIdx.x * 128 + threadIdx.x;
    int o0 = blockIdx.y * 16;
    int b  = blockIdx.z;
    for (int i = threadIdx.x; i < 16 * 80; i += 128)
        Ws[i / 80][i % 80] = W[(size_t)(o0 + i / 80) * 80 + (i % 80)];
    if (threadIdx.x < 16) Bs[threadIdx.x] = bias[o0 + threadIdx.x];
    __syncthreads();

    float acc[16];
    #pragma unroll
    for (int i = 0; i < 16; i++) acc[i] = Bs[i];
    const float* sp = speech + (size_t)b * 80 * LSEQ + l;
    for (int c = 0; c < 80; c++) {
        float sv = sp[(size_t)c * LSEQ];
        #pragma unroll
        for (int i = 0; i < 16; i++) acc[i] += Ws[i][c] * sv;
    }
    float* xp = x + ((size_t)b * CEMB + o0) * LSEQ + l;
    #pragma unroll
    for (int i = 0; i < 16; i++) xp[(size_t)i * LSEQ] = acc[i];
}

// ---------------- GroupNorm: x fp32 -> h2 (half2 c-pairs, l PG-permuted) -----
__global__ void group_norm_k(const float* __restrict__ x, const float* __restrict__ w,
                             const float* __restrict__ bb, uint32_t* __restrict__ h2) {
    int bg = blockIdx.x;
    int b = bg >> 5, g = bg & 31;
    const float* xp = x + ((size_t)b * CEMB + g * 32) * LSEQ;
    float s = 0.f, ss = 0.f;
    for (int i = threadIdx.x; i < 32 * LSEQ; i += 256) {
        float v = xp[i];
        s += v; ss += v * v;
    }
    #pragma unroll
    for (int o = 16; o; o >>= 1) {
        s  += __shfl_down_sync(0xffffffffu, s,  o);
        ss += __shfl_down_sync(0xffffffffu, ss, o);
    }
    __shared__ float shs[8], shss[8];
    __shared__ float smean, srstd;
    int wid = threadIdx.x >> 5, lane = threadIdx.x & 31;
    if (!lane) { shs[wid] = s; shss[wid] = ss; }
    __syncthreads();
    if (threadIdx.x == 0) {
        float S = 0.f, SS = 0.f;
        #pragma unroll
        for (int i = 0; i < 8; i++) { S += shs[i]; SS += shss[i]; }
        float mean = S / 32768.f;
        float var  = SS / 32768.f - mean * mean;
        smean = mean;
        srstd = rsqrtf(var + 1e-5f);
    }
    __syncthreads();
    float mean = smean, rstd = srstd;
    uint32_t* hp = h2 + ((size_t)b * KW + g * 16) * LSEQ;
    for (int i = threadIdx.x; i < 16 * LSEQ; i += 256) {
        int cp = i >> 10, l = i & 1023;
        int c = g * 32 + 2 * cp;
        float v0 = (xp[(size_t)(2 * cp) * LSEQ + l] - mean) * rstd * w[c] + bb[c];
        float v1 = (xp[(size_t)(2 * cp + 1) * LSEQ + l] - mean) * rstd * w[c + 1] + bb[c + 1];
        int lw = (l & ~31) | ((l & 7) << 2) | ((l >> 3) & 3);   // PG
        hp[(size_t)cp * LSEQ + lw] = packh2(v0, v1);
    }
}

// ---------------- fp16 MMA GEMM, 3-stage cp.async ----------------------------
// A = W2 words [m 128][kw 32 PK, stride 40] -> uint2 frags
// B = X2 words [kw 32][n 128 PG, stride 136] -> uint4 frags (n order natural after gather)
// K loop: 16 chunks of 32 words (=64 k). Tile 128x128, 8 warps (2m x 4n).
#define GEMM_AS_W   5120
#define GEMM_BUF_W  (GEMM_AS_W + 4352)
#define GEMM_SMEM   (GEMM_BUF_W * 3 * 4)

template <bool QKVOUT>
__global__ __launch_bounds__(256, 2) void gemm_wx_mma(
    const uint32_t* __restrict__ W2, const float* __restrict__ bias,
    const uint32_t* __restrict__ X2, const float* __restrict__ res,
    void* __restrict__ Yout, int O)
{
    extern __shared__ uint32_t smbuf[];
    int tid = threadIdx.x, lane = tid & 31, warp = tid >> 5;
    int g = lane >> 2, tg = lane & 3;
    int wm = warp >> 2, wn = warp & 3;
    int b = blockIdx.z, o0 = blockIdx.y << 7, l0 = blockIdx.x << 7;
    const uint32_t* Wp = W2 + (size_t)o0 * KW;
    const uint32_t* Xp = X2 + (size_t)b * KW * LSEQ + l0;
    uint32_t sb = (uint32_t)__cvta_generic_to_shared(smbuf);

    auto prefetch = [&](int kc, int bufi) {
        uint32_t base = sb + (uint32_t)bufi * (GEMM_BUF_W * 4u);
        int k0 = kc << 5;                           // word offset
        #pragma unroll
        for (int j = 0; j < 4; j++) {
            int idx = tid + (j << 8);
            int r = idx >> 3, c = (idx & 7) << 2;
            cpa16(base + (uint32_t)(r * 40 + c) * 4u, Wp + (size_t)r * KW + k0 + c);
        }
        #pragma unroll
        for (int j = 0; j < 4; j++) {
            int idx = tid + (j << 8);
            int r2 = idx >> 5, c2 = (idx & 31) << 2;
            cpa16(base + (uint32_t)(GEMM_AS_W + r2 * 136 + c2) * 4u,
                  Xp + (size_t)(k0 + r2) * LSEQ + c2);
        }
        cpa_commit();
    };

    float acc[4][4][4] = {};
    prefetch(0, 0);
    prefetch(1, 1);
    int use = 0, pre = 2;

    for (int kc = 0; kc < 16; kc++) {
        if (kc < 14) cpa_wait<1>(); else cpa_wait<0>();
        __syncthreads();
        if (kc < 14) prefetch(kc + 2, pre);

        const uint32_t* As = smbuf + use * GEMM_BUF_W;
        const uint32_t* Bs = As + GEMM_AS_W;
        #pragma unroll
        for (int ks = 0; ks < 4; ks++) {
            int kk = ks << 3;
            uint2 aA[4], aB[4];
            #pragma unroll
            for (int mi = 0; mi < 4; mi++) {
                int row = wm * 64 + mi * 16 + g;
                aA[mi] = *(const uint2*)&As[row * 40 + kk + 2 * tg];        // (a0,a2)
                aB[mi] = *(const uint2*)&As[(row + 8) * 40 + kk + 2 * tg];  // (a1,a3)
            }
            uint4 b0 = *(const uint4*)&Bs[(kk + tg) * 136 + wn * 32 + (g << 2)];
            uint4 b1 = *(const uint4*)&Bs[(kk + tg + 4) * 136 + wn * 32 + (g << 2)];
            uint32_t bb0[4] = {b0.x, b0.y, b0.z, b0.w};
            uint32_t bb1[4] = {b1.x, b1.y, b1.z, b1.w};
            #pragma unroll
            for (int mi = 0; mi < 4; mi++)
                #pragma unroll
                for (int ni = 0; ni < 4; ni++)
                    mma_f16(acc[mi][ni], aA[mi].x, aB[mi].x, aA[mi].y, aB[mi].y,
                            bb0[ni], bb1[ni]);
        }
        use = (use == 2) ? 0 : use + 1;
        pre = (pre == 2) ? 0 : pre + 1;
    }

    // epilogue: n order NATURAL -> l = wn*32 + ni*8 + 2*tg (+1)
    #pragma unroll
    for (int mi = 0; mi < 4; mi++) {
        #pragma unroll
        for (int rr = 0; rr < 2; rr++) {
            int o = o0 + wm * 64 + mi * 16 + g + rr * 8;
            float bsv = bias[o];
            #pragma unroll
            for (int ni = 0; ni < 4; ni++) {
                int la = wn * 32 + ni * 8 + (tg << 1);
                float v0 = acc[mi][ni][rr * 2]     + bsv;
                float v1 = acc[mi][ni][rr * 2 + 1] + bsv;
                if (QKVOUT) {
                    // route into per-head Q2[c/2][t] / K2[c/2][s] / V2[c][s/2]
                    uint32_t* Y2 = (uint32_t*)Yout;
                    int hh = o / 192, r = o - hh * 192;
                    size_t headbase = ((size_t)b * 1536 + hh * 96) * LSEQ;  // words
                    int lg = l0 + la;
                    if (r < 128) {
                        __half* hp = (__half*)Y2;
                        size_t hi = 2 * (headbase + (size_t)(r >> 1) * LSEQ + lg) + (r & 1);
                        hp[hi]     = __float2half_rn(v0);
                        hp[hi + 2] = __float2half_rn(v1);
                    } else {
                        int c = r - 128;
                        // V region starts AFTER Q/K (64 word-rows x LSEQ); rows stride KW
                        Y2[headbase + (size_t)64 * LSEQ + (size_t)c * KW + (lg >> 1)]
                            = packh2(v0, v1);
                    }
                } else {
                    float* Y = (float*)Yout;
                    size_t rowoff = ((size_t)b * O + o) * LSEQ + l0 + la;
                    float2 rv = *(const float2*)(res + rowoff);
                    *(float2*)(Y + rowoff) = make_float2(v0 + rv.x, v1 + rv.y);
                }
            }
        }
    }
}

// ---------------- fused flash attention (fp16 packed operands) ---------------
// smem words: Qs[32 kw][136], Ks[32][136], Vs[64 c][68], Ps[128 t][68]
#define FA_QS 0
#define FA_KS 4352
#define FA_VS 8704
#define FA_PS 13056
#define FA_SMEM ((13056 + 128 * 68) * 4)

__global__ __launch_bounds__(256, 1) void flash_attn(
    const uint32_t* __restrict__ qkv2, uint32_t* __restrict__ ao2)
{
    extern __shared__ uint32_t sm[];
    uint32_t* Qs = sm + FA_QS;
    uint32_t* Ks = sm + FA_KS;
    uint32_t* Vs = sm + FA_VS;
    uint32_t* Ps = sm + FA_PS;
    uint32_t fb = (uint32_t)__cvta_generic_to_shared(sm);

    int tid = threadIdx.x, lane = tid & 31, warp = tid >> 5;
    int g = lane >> 2, tg = lane & 3;
    int tw = warp << 4;
    int bh = blockIdx.y, b = bh >> 4, hh = bh & 15;
    int t0 = blockIdx.x << 7;
    const uint32_t* Qw = qkv2 + ((size_t)b * 1536 + hh * 96) * LSEQ;
    const uint32_t* Kw = Qw + 32 * LSEQ;
    const uint32_t* Vw = Qw + 64 * LSEQ;       // rows c, stride KW words

    // prologue: Q tile + first K/V tile
    #pragma unroll
    for (int j = 0; j < 4; j++) {
        int idx = tid + (j << 8);
        int r = idx >> 5, c4 = (idx & 31) << 2;           // Q/K: 32 rows x 128 words
        cpa16(fb + (uint32_t)(FA_QS + r * 136 + c4) * 4u, Qw + (size_t)r * LSEQ + t0 + c4);
        cpa16(fb + (uint32_t)(FA_KS + r * 136 + c4) * 4u, Kw + (size_t)r * LSEQ + c4);
        int rv = idx >> 4, cv = (idx & 15) << 2;          // V: 64 rows x 64 words
        cpa16(fb + (uint32_t)(FA_VS + rv * 68 + cv) * 4u, Vw + (size_t)rv * KW + cv);
    }
    cpa_commit();

    float accO[8][4] = {};
    float m0 = -1e30f, m1 = -1e30f, l0 = 0.f, l1 = 0.f;

    for (int s0 = 0; s0 < LSEQ; s0 += 128) {
        cpa_wait<0>();
        __syncthreads();

        // S[16t x 128s] per warp: 4 k-steps over 32 kw
        float accS[16][4] = {};
        #pragma unroll
        for (int kk = 0; kk < 4; kk++) {
            const uint32_t* p = &Qs[(kk * 8 + tg) * 136 + tw + g];
            uint32_t a0 = p[0], a1 = p[8], a2 = p[4 * 136], a3 = p[4 * 136 + 8];
            #pragma unroll
            for (int ni = 0; ni < 16; ni++) {
                const uint32_t* q = &Ks[(kk * 8 + tg) * 136 + ni * 8 + g];
                mma_f16(accS[ni], a0, a1, a2, a3, q[0], q[4 * 136]);
            }
        }

        // online softmax: rows t = tw+g (comp 0,1), tw+g+8 (comp 2,3); s natural
        float tm0 = -1e30f, tm1 = -1e30f;
        #pragma unroll
        for (int ni = 0; ni < 16; ni++) {
            #pragma unroll
            for (int v = 0; v < 4; v++) accS[ni][v] *= 0.125f;
            tm0 = fmaxf(tm0, fmaxf(accS[ni][0], accS[ni][1]));
            tm1 = fmaxf(tm1, fmaxf(accS[ni][2], accS[ni][3]));
        }
        tm0 = fmaxf(tm0, __shfl_xor_sync(0xffffffffu, tm0, 1));
        tm0 = fmaxf(tm0, __shfl_xor_sync(0xffffffffu, tm0, 2));
        tm1 = fmaxf(tm1, __shfl_xor_sync(0xffffffffu, tm1, 1));
        tm1 = fmaxf(tm1, __shfl_xor_sync(0xffffffffu, tm1, 2));
        float nm0 = fmaxf(m0, tm0), nm1 = fmaxf(m1, tm1);
        float f0 = __expf(m0 - nm0), f1 = __expf(m1 - nm1);
        float ts0 = 0.f, ts1 = 0.f;
        #pragma unroll
        for (int ni = 0; ni < 16; ni++) {
            float p0 = __expf(accS[ni][0] - nm0);
            float p1 = __expf(accS[ni][1] - nm0);
            float p2 = __expf(accS[ni][2] - nm1);
            float p3 = __expf(accS[ni][3] - nm1);
            ts0 += p0 + p1; ts1 += p2 + p3;
            Ps[(tw + g) * 68 + ni * 4 + tg]     = packh2(p0, p1);   // s pair (ni*8+2tg, +1)
            Ps[(tw + g + 8) * 68 + ni * 4 + tg] = packh2(p2, p3);
        }
        ts0 += __shfl_xor_sync(0xffffffffu, ts0, 1);
        ts0 += __shfl_xor_sync(0xffffffffu, ts0, 2);
        ts1 += __shfl_xor_sync(0xffffffffu, ts1, 1);
        ts1 += __shfl_xor_sync(0xffffffffu, ts1, 2);
        l0 = l0 * f0 + ts0;
        l1 = l1 * f1 + ts1;
        m0 = nm0; m1 = nm1;
        #pragma unroll
        for (int ni = 0; ni < 8; ni++) {
            accO[ni][0] *= f0; accO[ni][1] *= f0;
            accO[ni][2] *= f1; accO[ni][3] *= f1;
        }
        __syncwarp();

        // O[16t x 64c] += P V^T : 8 k-steps over 64 sw; P and V both s-pair packed
        #pragma unroll
        for (int kk = 0; kk < 8; kk++) {
            int pa = (tw + g) * 68 + kk * 8 + tg;
            uint32_t a0 = Ps[pa], a1 = Ps[pa + 8 * 68], a2 = Ps[pa + 4], a3 = Ps[pa + 8 * 68 + 4];
            #pragma unroll
            for (int ni = 0; ni < 8; ni++) {
                int vb = (ni * 8 + g) * 68 + kk * 8 + tg;
                mma_f16(accO[ni], a0, a1, a2, a3, Vs[vb], Vs[vb + 4]);
            }
        }
        __syncthreads();

        if (s0 + 128 < LSEQ) {
            int snw = (s0 + 128) >> 1;    // word offset for V, element offset for K
            #pragma unroll
            for (int j = 0; j < 4; j++) {
                int idx = tid + (j << 8);
                int r = idx >> 5, c4 = (idx & 31) << 2;
                cpa16(fb + (uint32_t)(FA_KS + r * 136 + c4) * 4u,
                      Kw + (size_t)r * LSEQ + s0 + 128 + c4);
                int rv = idx >> 4, cv = (idx & 15) << 2;
                cpa16(fb + (uint32_t)(FA_VS + rv * 68 + cv) * 4u,
                      Vw + (size_t)rv * KW + snw + cv);
            }
            cpa_commit();
        }
    }

    // epilogue: t natural; c pairs adjacent (comp 0/1); store ao2[c/2][PG(t)]
    float inv0 = 1.0f / l0, inv1 = 1.0f / l1;
    int tA = t0 + tw + g;
    int tB = tA + 8;
    int colA = (tA & ~31) | ((tA & 7) << 2) | ((tA >> 3) & 3);
    int colB = (tB & ~31) | ((tB & 7) << 2) | ((tB >> 3) & 3);
    size_t base = ((size_t)b * KW + hh * 32) * LSEQ;
    #pragma unroll
    for (int ni = 0; ni < 8; ni++) {
        int cw = ni * 4 + tg;                  // c pair (ni*8+2tg, +1) -> word row
        ao2[base + (size_t)cw * LSEQ + colA] = packh2(accO[ni][0] * inv0, accO[ni][1] * inv0);
        ao2[base + (size_t)cw * LSEQ + colB] = packh2(accO[ni][2] * inv1, accO[ni][3] * inv1);
    }
}

// ---------------- final: out[b,c] = x[b,c,0] --------------------------------
__global__ void take_col0(const float* __restrict__ x, float* __restrict__ out) {
    int i = blockIdx.x * 256 + threadIdx.x;
    out[i] = x[(size_t)i * LSEQ];
}

extern "C" void kernel_launch(void* const* d_in, const int* in_sizes, int n_in,
                              void* d_out, int out_size) {
    const float* speech = (const float*)d_in[0];
    const float* init_w = (const float*)d_in[1];
    const float* init_b = (const float*)d_in[2];
    const float* gn_w   = (const float*)d_in[3];
    const float* gn_b   = (const float*)d_in[4];
    const float* qkv_w  = (const float*)d_in[5];
    const float* qkv_b  = (const float*)d_in[6];
    const float* proj_w = (const float*)d_in[7];
    const float* proj_b = (const float*)d_in[8];

    float *x;
    uint32_t *h2, *qkv2, *ao2, *wq2, *wp2;
    cudaGetSymbolAddress((void**)&x,    g_x);
    cudaGetSymbolAddress((void**)&h2,   g_h2);
    cudaGetSymbolAddress((void**)&qkv2, g_qkv2);
    cudaGetSymbolAddress((void**)&ao2,  g_ao2);
    cudaGetSymbolAddress((void**)&wq2,  g_wq2);
    cudaGetSymbolAddress((void**)&wp2,  g_wp2);

    cudaFuncSetAttribute(flash_attn, cudaFuncAttributeMaxDynamicSharedMemorySize, FA_SMEM);
    cudaFuncSetAttribute(gemm_wx_mma<true>,  cudaFuncAttributeMaxDynamicSharedMemorySize, GEMM_SMEM);
    cudaFuncSetAttribute(gemm_wx_mma<false>, cudaFuncAttributeMaxDynamicSharedMemorySize, GEMM_SMEM);

    pack_w<<<2048, 256>>>(qkv_w,  wq2, 6 * 3 * CEMB * KW);
    pack_w<<<1024, 256>>>(proj_w, wp2, 6 * CEMB * KW);

    init_gemm<<<dim3(LSEQ / 128, CEMB / 16, BB), 128>>>(speech, init_w, init_b, x);

    for (int i = 0; i < 6; i++) {
        group_norm_k<<<BB * NGRP, 256>>>(x, gn_w + (size_t)i * CEMB, gn_b + (size_t)i * CEMB, h2);
        gemm_wx_mma<true><<<dim3(LSEQ / 128, 3 * CEMB / 128, BB), 256, GEMM_SMEM>>>(
            wq2 + (size_t)i * 3 * CEMB * KW, qkv_b + (size_t)i * 3 * CEMB,
            h2, nullptr, qkv2, 3 * CEMB);
        flash_attn<<<dim3(LSEQ / 128, BB * NH), 256, FA_SMEM>>>(qkv2, ao2);
        gemm_wx_mma<false><<<dim3(LSEQ / 128, CEMB / 128, BB), 256, GEMM_SMEM>>>(
            wp2 + (size_t)i * CEMB * KW, proj_b + (size_t)i * CEMB,
            ao2, x, x, CEMB);
    }

    take_col0<<<32, 256>>>(x, (float*)d_out);
}

// round 9
// speedup vs baseline: 1.8552x; 1.0508x over previous
#include <cuda_runtime.h>
#include <cuda_fp16.h>
#include <math.h>
#include <stdint.h>

#define LSEQ 1024
#define CEMB 1024
#define KD   1024
#define KW   512      // k in half2 words
#define BB   8
#define NH   16
#define DH   64
#define NGRP 32

// ---------------- static scratch (device globals; no allocation) -------------
__device__ float    g_x   [(size_t)BB * CEMB * LSEQ];          // natural fp32
__device__ uint32_t g_h2  [(size_t)BB * KW * LSEQ];            // half2[c/2][l PG]
__device__ uint32_t g_qkv2[(size_t)BB * 1536 * LSEQ];          // per head: Q2[32][1024],K2[32][1024],V2[64][512]
__device__ uint32_t g_ao2 [(size_t)BB * KW * LSEQ];            // half2[c/2][t PG]
__device__ uint32_t g_wq2 [(size_t)6 * 3 * CEMB * KW];         // half2, PK word-perm
__device__ uint32_t g_wp2 [(size_t)6 * CEMB * KW];             // half2, PK word-perm

// PK (word idx within 8): stored = (kw&~7)|((kw&3)<<1)|((kw>>2)&1)  -> (tg, tg+4) adjacent
// PG (within 32): stored  = (l&~31)|((l&7)<<2)|((l>>3)&3)           -> lane-g quads adjacent

// ---------------- helpers ----------------------------------------------------
__device__ __forceinline__ void mma_f16(float (&c)[4],
                                        uint32_t a0, uint32_t a1, uint32_t a2, uint32_t a3,
                                        uint32_t b0, uint32_t b1) {
    asm volatile(
        "mma.sync.aligned.m16n8k16.row.col.f32.f16.f16.f32 "
        "{%0,%1,%2,%3},{%4,%5,%6,%7},{%8,%9},{%0,%1,%2,%3};"
        : "+f"(c[0]), "+f"(c[1]), "+f"(c[2]), "+f"(c[3])
        : "r"(a0), "r"(a1), "r"(a2), "r"(a3), "r"(b0), "r"(b1));
}

__device__ __forceinline__ uint32_t packh2(float a, float b) {
    __half2 h = __floats2half2_rn(a, b);
    return *(uint32_t*)&h;
}

__device__ __forceinline__ void cpa16(uint32_t dst, const void* src) {
    asm volatile("cp.async.cg.shared.global [%0], [%1], 16;" :: "r"(dst), "l"(src));
}
__device__ __forceinline__ void cpa_commit() {
    asm volatile("cp.async.commit_group;" ::);
}
template <int N>
__device__ __forceinline__ void cpa_wait() {
    asm volatile("cp.async.wait_group %0;" :: "n"(N));
}

// ---------------- weight pack: fp32 [o][k] -> half2 words [o][kw PK] ---------
__global__ void pack_w(const float* __restrict__ in, uint32_t* __restrict__ out, int nw) {
    for (int i = blockIdx.x * 256 + threadIdx.x; i < nw; i += gridDim.x * 256) {
        int o = i >> 9, kws = i & (KW - 1);
        int kw = (kws & ~7) | ((kws >> 1) & 3) | ((kws & 1) << 2);   // PK inverse
        const float* p = in + (size_t)o * KD + 2 * kw;
        out[i] = packh2(p[0], p[1]);
    }
}

// ---------------- init projection (x natural fp32) ---------------------------
__global__ void init_gemm(const float* __restrict__ speech, const float* __restrict__ W,
                          const float* __restrict__ bias, float* __restrict__ x) {
    __shared__ float Ws[16][80];
    __shared__ float Bs[16];
    int l  = blockIdx.x * 128 + threadIdx.x;
    int o0 = blockIdx.y * 16;
    int b  = blockIdx.z;
    for (int i = threadIdx.x; i < 16 * 80; i += 128)
        Ws[i / 80][i % 80] = W[(size_t)(o0 + i / 80) * 80 + (i % 80)];
    if (threadIdx.x < 16) Bs[threadIdx.x] = bias[o0 + threadIdx.x];
    __syncthreads();

    float acc[16];
    #pragma unroll
    for (int i = 0; i < 16; i++) acc[i] = Bs[i];
    const float* sp = speech + (size_t)b * 80 * LSEQ + l;
    for (int c = 0; c < 80; c++) {
        float sv = sp[(size_t)c * LSEQ];
        #pragma unroll
        for (int i = 0; i < 16; i++) acc[i] += Ws[i][c] * sv;
    }
    float* xp = x + ((size_t)b * CEMB + o0) * LSEQ + l;
    #pragma unroll
    for (int i = 0; i < 16; i++) xp[(size_t)i * LSEQ] = acc[i];
}

// ---------------- GroupNorm: x fp32 -> h2 (half2 c-pairs, l PG-permuted) -----
__global__ void group_norm_k(const float* __restrict__ x, const float* __restrict__ w,
                             const float* __restrict__ bb, uint32_t* __restrict__ h2) {
    int bg = blockIdx.x;
    int b = bg >> 5, g = bg & 31;
    const float* xp = x + ((size_t)b * CEMB + g * 32) * LSEQ;
    float s = 0.f, ss = 0.f;
    for (int i = threadIdx.x; i < 32 * LSEQ; i += 256) {
        float v = xp[i];
        s += v; ss += v * v;
    }
    #pragma unroll
    for (int o = 16; o; o >>= 1) {
        s  += __shfl_down_sync(0xffffffffu, s,  o);
        ss += __shfl_down_sync(0xffffffffu, ss, o);
    }
    __shared__ float shs[8], shss[8];
    __shared__ float smean, srstd;
    int wid = threadIdx.x >> 5, lane = threadIdx.x & 31;
    if (!lane) { shs[wid] = s; shss[wid] = ss; }
    __syncthreads();
    if (threadIdx.x == 0) {
        float S = 0.f, SS = 0.f;
        #pragma unroll
        for (int i = 0; i < 8; i++) { S += shs[i]; SS += shss[i]; }
        float mean = S / 32768.f;
        float var  = SS / 32768.f - mean * mean;
        smean = mean;
        srstd = rsqrtf(var + 1e-5f);
    }
    __syncthreads();
    float mean = smean, rstd = srstd;
    uint32_t* hp = h2 + ((size_t)b * KW + g * 16) * LSEQ;
    for (int i = threadIdx.x; i < 16 * LSEQ; i += 256) {
        int cp = i >> 10, l = i & 1023;
        int c = g * 32 + 2 * cp;
        float v0 = (xp[(size_t)(2 * cp) * LSEQ + l] - mean) * rstd * w[c] + bb[c];
        float v1 = (xp[(size_t)(2 * cp + 1) * LSEQ + l] - mean) * rstd * w[c + 1] + bb[c + 1];
        int lw = (l & ~31) | ((l & 7) << 2) | ((l >> 3) & 3);   // PG
        hp[(size_t)cp * LSEQ + lw] = packh2(v0, v1);
    }
}

// ---------------- fp16 MMA GEMM, 3-stage cp.async ----------------------------
// A = W2 words [m 128][kw 32 PK, stride 40] -> uint2 frags
// B = X2 words [kw 32][n 128 PG, stride 136] -> uint4 frags (n order natural after gather)
// K loop: 16 chunks of 32 words (=64 k). Tile 128x128, 8 warps (2m x 4n).
#define GEMM_AS_W   5120
#define GEMM_BUF_W  (GEMM_AS_W + 4352)
#define GEMM_SMEM   (GEMM_BUF_W * 3 * 4)

template <bool QKVOUT>
__global__ __launch_bounds__(256, 2) void gemm_wx_mma(
    const uint32_t* __restrict__ W2, const float* __restrict__ bias,
    const uint32_t* __restrict__ X2, const float* __restrict__ res,
    void* __restrict__ Yout, int O)
{
    extern __shared__ uint32_t smbuf[];
    int tid = threadIdx.x, lane = tid & 31, warp = tid >> 5;
    int g = lane >> 2, tg = lane & 3;
    int wm = warp >> 2, wn = warp & 3;
    int b = blockIdx.z, o0 = blockIdx.y << 7, l0 = blockIdx.x << 7;
    const uint32_t* Wp = W2 + (size_t)o0 * KW;
    const uint32_t* Xp = X2 + (size_t)b * KW * LSEQ + l0;
    uint32_t sb = (uint32_t)__cvta_generic_to_shared(smbuf);

    auto prefetch = [&](int kc, int bufi) {
        uint32_t base = sb + (uint32_t)bufi * (GEMM_BUF_W * 4u);
        int k0 = kc << 5;                           // word offset
        #pragma unroll
        for (int j = 0; j < 4; j++) {
            int idx = tid + (j << 8);
            int r = idx >> 3, c = (idx & 7) << 2;
            cpa16(base + (uint32_t)(r * 40 + c) * 4u, Wp + (size_t)r * KW + k0 + c);
        }
        #pragma unroll
        for (int j = 0; j < 4; j++) {
            int idx = tid + (j << 8);
            int r2 = idx >> 5, c2 = (idx & 31) << 2;
            cpa16(base + (uint32_t)(GEMM_AS_W + r2 * 136 + c2) * 4u,
                  Xp + (size_t)(k0 + r2) * LSEQ + c2);
        }
        cpa_commit();
    };

    float acc[4][4][4] = {};
    prefetch(0, 0);
    prefetch(1, 1);
    int use = 0, pre = 2;

    for (int kc = 0; kc < 16; kc++) {
        if (kc < 14) cpa_wait<1>(); else cpa_wait<0>();
        __syncthreads();
        if (kc < 14) prefetch(kc + 2, pre);

        const uint32_t* As = smbuf + use * GEMM_BUF_W;
        const uint32_t* Bs = As + GEMM_AS_W;
        #pragma unroll
        for (int ks = 0; ks < 4; ks++) {
            int kk = ks << 3;
            uint2 aA[4], aB[4];
            #pragma unroll
            for (int mi = 0; mi < 4; mi++) {
                int row = wm * 64 + mi * 16 + g;
                aA[mi] = *(const uint2*)&As[row * 40 + kk + 2 * tg];        // (a0,a2)
                aB[mi] = *(const uint2*)&As[(row + 8) * 40 + kk + 2 * tg];  // (a1,a3)
            }
            uint4 b0 = *(const uint4*)&Bs[(kk + tg) * 136 + wn * 32 + (g << 2)];
            uint4 b1 = *(const uint4*)&Bs[(kk + tg + 4) * 136 + wn * 32 + (g << 2)];
            uint32_t bb0[4] = {b0.x, b0.y, b0.z, b0.w};
            uint32_t bb1[4] = {b1.x, b1.y, b1.z, b1.w};
            #pragma unroll
            for (int mi = 0; mi < 4; mi++)
                #pragma unroll
                for (int ni = 0; ni < 4; ni++)
                    mma_f16(acc[mi][ni], aA[mi].x, aB[mi].x, aA[mi].y, aB[mi].y,
                            bb0[ni], bb1[ni]);
        }
        use = (use == 2) ? 0 : use + 1;
        pre = (pre == 2) ? 0 : pre + 1;
    }

    // epilogue: n order NATURAL -> l = wn*32 + ni*8 + 2*tg (+1)
    #pragma unroll
    for (int mi = 0; mi < 4; mi++) {
        #pragma unroll
        for (int rr = 0; rr < 2; rr++) {
            int o = o0 + wm * 64 + mi * 16 + g + rr * 8;
            float bsv = bias[o];
            #pragma unroll
            for (int ni = 0; ni < 4; ni++) {
                int la = wn * 32 + ni * 8 + (tg << 1);
                float v0 = acc[mi][ni][rr * 2]     + bsv;
                float v1 = acc[mi][ni][rr * 2 + 1] + bsv;
                if (QKVOUT) {
                    // route into per-head Q2[c/2][t] / K2[c/2][s] / V2[c][s/2]
                    uint32_t* Y2 = (uint32_t*)Yout;
                    int hh = o / 192, r = o - hh * 192;
                    size_t headbase = ((size_t)b * 1536 + hh * 96) * LSEQ;  // words
                    int lg = l0 + la;
                    if (r < 128) {
                        __half* hp = (__half*)Y2;
                        size_t hi = 2 * (headbase + (size_t)(r >> 1) * LSEQ + lg) + (r & 1);
                        hp[hi]     = __float2half_rn(v0);
                        hp[hi + 2] = __float2half_rn(v1);
                    } else {
                        int c = r - 128;
                        // V region starts AFTER Q/K (64 word-rows x LSEQ); rows stride KW
                        Y2[headbase + (size_t)64 * LSEQ + (size_t)c * KW + (lg >> 1)]
                            = packh2(v0, v1);
                    }
                } else {
                    float* Y = (float*)Yout;
                    size_t rowoff = ((size_t)b * O + o) * LSEQ + l0 + la;
                    float2 rv = *(const float2*)(res + rowoff);
                    *(float2*)(Y + rowoff) = make_float2(v0 + rv.x, v1 + rv.y);
                }
            }
        }
    }
}

// ---------------- fused flash attention (fp16, double-buffered K/V) ----------
// smem words: Qs[32][136], Ks[2][32][136], Vs[2][64][68], Ps[128][68]
#define FA_QS 0
#define FA_KS 4352                     // two buffers of 4352 words
#define FA_VS 13056                    // two buffers of 4352 words
#define FA_PS 21760
#define FA_SMEM ((21760 + 128 * 68) * 4)

__global__ __launch_bounds__(256, 1) void flash_attn(
    const uint32_t* __restrict__ qkv2, uint32_t* __restrict__ ao2)
{
    extern __shared__ uint32_t sm[];
    uint32_t* Qs = sm + FA_QS;
    uint32_t* Ps = sm + FA_PS;
    uint32_t fb = (uint32_t)__cvta_generic_to_shared(sm);

    int tid = threadIdx.x, lane = tid & 31, warp = tid >> 5;
    int g = lane >> 2, tg = lane & 3;
    int tw = warp << 4;
    int bh = blockIdx.y, b = bh >> 4, hh = bh & 15;
    int t0 = blockIdx.x << 7;
    const uint32_t* Qw = qkv2 + ((size_t)b * 1536 + hh * 96) * LSEQ;
    const uint32_t* Kw = Qw + 32 * LSEQ;
    const uint32_t* Vw = Qw + 64 * LSEQ;       // rows c, stride KW words

    // issue K/V loads for key-tile s0 into buffer p
    auto load_kv = [&](int s0, int p) {
        uint32_t kbase = fb + (uint32_t)(FA_KS + p * 4352) * 4u;
        uint32_t vbase = fb + (uint32_t)(FA_VS + p * 4352) * 4u;
        int snw = s0 >> 1;
        #pragma unroll
        for (int j = 0; j < 4; j++) {
            int idx = tid + (j << 8);
            int r = idx >> 5, c4 = (idx & 31) << 2;           // K: 32 rows x 128 words
            cpa16(kbase + (uint32_t)(r * 136 + c4) * 4u, Kw + (size_t)r * LSEQ + s0 + c4);
            int rv = idx >> 4, cv = (idx & 15) << 2;          // V: 64 rows x 64 words
            cpa16(vbase + (uint32_t)(rv * 68 + cv) * 4u, Vw + (size_t)rv * KW + snw + cv);
        }
        cpa_commit();
    };

    // prologue: Q tile + first K/V tile (buffer 0)
    #pragma unroll
    for (int j = 0; j < 4; j++) {
        int idx = tid + (j << 8);
        int r = idx >> 5, c4 = (idx & 31) << 2;
        cpa16(fb + (uint32_t)(FA_QS + r * 136 + c4) * 4u, Qw + (size_t)r * LSEQ + t0 + c4);
    }
    load_kv(0, 0);

    float accO[8][4] = {};
    float m0 = -1e30f, m1 = -1e30f, l0 = 0.f, l1 = 0.f;

    for (int it = 0; it < 8; it++) {
        int p = it & 1;
        const uint32_t* Ks = sm + FA_KS + p * 4352;
        const uint32_t* Vs = sm + FA_VS + p * 4352;

        cpa_wait<0>();
        __syncthreads();

        // S[16t x 128s] per warp: 4 k-steps over 32 kw
        float accS[16][4] = {};
        #pragma unroll
        for (int kk = 0; kk < 4; kk++) {
            const uint32_t* pq = &Qs[(kk * 8 + tg) * 136 + tw + g];
            uint32_t a0 = pq[0], a1 = pq[8], a2 = pq[4 * 136], a3 = pq[4 * 136 + 8];
            #pragma unroll
            for (int ni = 0; ni < 16; ni++) {
                const uint32_t* q = &Ks[(kk * 8 + tg) * 136 + ni * 8 + g];
                mma_f16(accS[ni], a0, a1, a2, a3, q[0], q[4 * 136]);
            }
        }

        // K/V consumed from buffer p only beyond this point for THIS tile's S;
        // buffer p^1 is dead (all warps passed the top barrier) -> prefetch now,
        // overlapping the load with softmax + PV below.
        if (it < 7) load_kv((it + 1) << 7, p ^ 1);

        // online softmax: rows t = tw+g (comp 0,1), tw+g+8 (comp 2,3); s natural
        float tm0 = -1e30f, tm1 = -1e30f;
        #pragma unroll
        for (int ni = 0; ni < 16; ni++) {
            #pragma unroll
            for (int v = 0; v < 4; v++) accS[ni][v] *= 0.125f;
            tm0 = fmaxf(tm0, fmaxf(accS[ni][0], accS[ni][1]));
            tm1 = fmaxf(tm1, fmaxf(accS[ni][2], accS[ni][3]));
        }
        tm0 = fmaxf(tm0, __shfl_xor_sync(0xffffffffu, tm0, 1));
        tm0 = fmaxf(tm0, __shfl_xor_sync(0xffffffffu, tm0, 2));
        tm1 = fmaxf(tm1, __shfl_xor_sync(0xffffffffu, tm1, 1));
        tm1 = fmaxf(tm1, __shfl_xor_sync(0xffffffffu, tm1, 2));
        float nm0 = fmaxf(m0, tm0), nm1 = fmaxf(m1, tm1);
        float f0 = __expf(m0 - nm0), f1 = __expf(m1 - nm1);
        float ts0 = 0.f, ts1 = 0.f;
        #pragma unroll
        for (int ni = 0; ni < 16; ni++) {
            float p0 = __expf(accS[ni][0] - nm0);
            float p1 = __expf(accS[ni][1] - nm0);
            float p2 = __expf(accS[ni][2] - nm1);
            float p3 = __expf(accS[ni][3] - nm1);
            ts0 += p0 + p1; ts1 += p2 + p3;
            Ps[(tw + g) * 68 + ni * 4 + tg]     = packh2(p0, p1);   // s pair (ni*8+2tg, +1)
            Ps[(tw + g + 8) * 68 + ni * 4 + tg] = packh2(p2, p3);
        }
        ts0 += __shfl_xor_sync(0xffffffffu, ts0, 1);
        ts0 += __shfl_xor_sync(0xffffffffu, ts0, 2);
        ts1 += __shfl_xor_sync(0xffffffffu, ts1, 1);
        ts1 += __shfl_xor_sync(0xffffffffu, ts1, 2);
        l0 = l0 * f0 + ts0;
        l1 = l1 * f1 + ts1;
        m0 = nm0; m1 = nm1;
        #pragma unroll
        for (int ni = 0; ni < 8; ni++) {
            accO[ni][0] *= f0; accO[ni][1] *= f0;
            accO[ni][2] *= f1; accO[ni][3] *= f1;
        }
        __syncwarp();   // Ps is warp-private: writes above, reads below, same warp

        // O[16t x 64c] += P V^T : 8 k-steps over 64 sw; P and V both s-pair packed
        #pragma unroll
        for (int kk = 0; kk < 8; kk++) {
            int pa = (tw + g) * 68 + kk * 8 + tg;
            uint32_t a0 = Ps[pa], a1 = Ps[pa + 8 * 68], a2 = Ps[pa + 4], a3 = Ps[pa + 8 * 68 + 4];
            #pragma unroll
            for (int ni = 0; ni < 8; ni++) {
                int vb = (ni * 8 + g) * 68 + kk * 8 + tg;
                mma_f16(accO[ni], a0, a1, a2, a3, Vs[vb], Vs[vb + 4]);
            }
        }
        // no end-of-iter barrier: next iter's top barrier orders buffer reuse
    }

    // epilogue: t natural; c pairs adjacent (comp 0/1); store ao2[c/2][PG(t)]
    float inv0 = 1.0f / l0, inv1 = 1.0f / l1;
    int tA = t0 + tw + g;
    int tB = tA + 8;
    int colA = (tA & ~31) | ((tA & 7) << 2) | ((tA >> 3) & 3);
    int colB = (tB & ~31) | ((tB & 7) << 2) | ((tB >> 3) & 3);
    size_t base = ((size_t)b * KW + hh * 32) * LSEQ;
    #pragma unroll
    for (int ni = 0; ni < 8; ni++) {
        int cw = ni * 4 + tg;                  // c pair (ni*8+2tg, +1) -> word row
        ao2[base + (size_t)cw * LSEQ + colA] = packh2(accO[ni][0] * inv0, accO[ni][1] * inv0);
        ao2[base + (size_t)cw * LSEQ + colB] = packh2(accO[ni][2] * inv1, accO[ni][3] * inv1);
    }
}

// ---------------- final: out[b,c] = x[b,c,0] --------------------------------
__global__ void take_col0(const float* __restrict__ x, float* __restrict__ out) {
    int i = blockIdx.x * 256 + threadIdx.x;
    out[i] = x[(size_t)i * LSEQ];
}

extern "C" void kernel_launch(void* const* d_in, const int* in_sizes, int n_in,
                              void* d_out, int out_size) {
    const float* speech = (const float*)d_in[0];
    const float* init_w = (const float*)d_in[1];
    const float* init_b = (const float*)d_in[2];
    const float* gn_w   = (const float*)d_in[3];
    const float* gn_b   = (const float*)d_in[4];
    const float* qkv_w  = (const float*)d_in[5];
    const float* qkv_b  = (const float*)d_in[6];
    const float* proj_w = (const float*)d_in[7];
    const float* proj_b = (const float*)d_in[8];

    float *x;
    uint32_t *h2, *qkv2, *ao2, *wq2, *wp2;
    cudaGetSymbolAddress((void**)&x,    g_x);
    cudaGetSymbolAddress((void**)&h2,   g_h2);
    cudaGetSymbolAddress((void**)&qkv2, g_qkv2);
    cudaGetSymbolAddress((void**)&ao2,  g_ao2);
    cudaGetSymbolAddress((void**)&wq2,  g_wq2);
    cudaGetSymbolAddress((void**)&wp2,  g_wp2);

    cudaFuncSetAttribute(flash_attn, cudaFuncAttributeMaxDynamicSharedMemorySize, FA_SMEM);
    cudaFuncSetAttribute(gemm_wx_mma<true>,  cudaFuncAttributeMaxDynamicSharedMemorySize, GEMM_SMEM);
    cudaFuncSetAttribute(gemm_wx_mma<false>, cudaFuncAttributeMaxDynamicSharedMemorySize, GEMM_SMEM);

    pack_w<<<2048, 256>>>(qkv_w,  wq2, 6 * 3 * CEMB * KW);
    pack_w<<<1024, 256>>>(proj_w, wp2, 6 * CEMB * KW);

    init_gemm<<<dim3(LSEQ / 128, CEMB / 16, BB), 128>>>(speech, init_w, init_b, x);

    for (int i = 0; i < 6; i++) {
        group_norm_k<<<BB * NGRP, 256>>>(x, gn_w + (size_t)i * CEMB, gn_b + (size_t)i * CEMB, h2);
        gemm_wx_mma<true><<<dim3(LSEQ / 128, 3 * CEMB / 128, BB), 256, GEMM_SMEM>>>(
            wq2 + (size_t)i * 3 * CEMB * KW, qkv_b + (size_t)i * 3 * CEMB,
            h2, nullptr, qkv2, 3 * CEMB);
        flash_attn<<<dim3(LSEQ / 128, BB * NH), 256, FA_SMEM>>>(qkv2, ao2);
        gemm_wx_mma<false><<<dim3(LSEQ / 128, CEMB / 128, BB), 256, GEMM_SMEM>>>(
            wp2 + (size_t)i * CEMB * KW, proj_b + (size_t)i * CEMB,
            ao2, x, x, CEMB);
    }

    take_col0<<<32, 256>>>(x, (float*)d_out);
}

// round 14
// speedup vs baseline: 2.0152x; 1.0862x over previous
#include <cuda_runtime.h>
#include <cuda_fp16.h>
#include <math.h>
#include <stdint.h>

#define LSEQ 1024
#define CEMB 1024
#define KD   1024
#define KW   512      // k in half2 words
#define BB   8
#define NH   16
#define DH   64
#define NGRP 32

// ---------------- static scratch (device globals; no allocation) -------------
__device__ float    g_x   [(size_t)BB * CEMB * LSEQ];          // natural fp32
__device__ uint32_t g_h2  [(size_t)BB * KW * LSEQ];            // half2[c/2][l PG]
__device__ uint32_t g_qkv2[(size_t)BB * 1536 * LSEQ];          // per head: Q2[32][1024],K2[32][1024],V2[64][512]
__device__ uint32_t g_ao2 [(size_t)BB * KW * LSEQ];            // half2[c/2][t PG]
__device__ uint32_t g_wq2 [(size_t)6 * 3 * CEMB * KW];         // half2, PK word-perm
__device__ uint32_t g_wp2 [(size_t)6 * CEMB * KW];             // half2, PK word-perm

// PK (word idx within 8): stored = (kw&~7)|((kw&3)<<1)|((kw>>2)&1)  -> (tg, tg+4) adjacent
// PG (within 32): stored  = (l&~31)|((l&7)<<2)|((l>>3)&3)           -> lane-g quads adjacent

// ---------------- helpers ----------------------------------------------------
__device__ __forceinline__ void mma_f16(float (&c)[4],
                                        uint32_t a0, uint32_t a1, uint32_t a2, uint32_t a3,
                                        uint32_t b0, uint32_t b1) {
    asm volatile(
        "mma.sync.aligned.m16n8k16.row.col.f32.f16.f16.f32 "
        "{%0,%1,%2,%3},{%4,%5,%6,%7},{%8,%9},{%0,%1,%2,%3};"
        : "+f"(c[0]), "+f"(c[1]), "+f"(c[2]), "+f"(c[3])
        : "r"(a0), "r"(a1), "r"(a2), "r"(a3), "r"(b0), "r"(b1));
}

__device__ __forceinline__ uint32_t packh2(float a, float b) {
    __half2 h = __floats2half2_rn(a, b);
    return *(uint32_t*)&h;
}

__device__ __forceinline__ void cpa16(uint32_t dst, const void* src) {
    asm volatile("cp.async.cg.shared.global [%0], [%1], 16;" :: "r"(dst), "l"(src));
}
__device__ __forceinline__ void cpa_commit() {
    asm volatile("cp.async.commit_group;" ::);
}
template <int N>
__device__ __forceinline__ void cpa_wait() {
    asm volatile("cp.async.wait_group %0;" :: "n"(N));
}

// ---------------- weight pack: fp32 [o][k] -> half2 words [o][kw PK] ---------
__global__ void pack_w(const float* __restrict__ in, uint32_t* __restrict__ out, int nw) {
    for (int i = blockIdx.x * 256 + threadIdx.x; i < nw; i += gridDim.x * 256) {
        int o = i >> 9, kws = i & (KW - 1);
        int kw = (kws & ~7) | ((kws >> 1) & 3) | ((kws & 1) << 2);   // PK inverse
        const float* p = in + (size_t)o * KD + 2 * kw;
        out[i] = packh2(p[0], p[1]);
    }
}

// ---------------- init projection (x natural fp32) ---------------------------
__global__ void init_gemm(const float* __restrict__ speech, const float* __restrict__ W,
                          const float* __restrict__ bias, float* __restrict__ x) {
    __shared__ float Ws[16][80];
    __shared__ float Bs[16];
    int l  = blockIdx.x * 128 + threadIdx.x;
    int o0 = blockIdx.y * 16;
    int b  = blockIdx.z;
    for (int i = threadIdx.x; i < 16 * 80; i += 128)
        Ws[i / 80][i % 80] = W[(size_t)(o0 + i / 80) * 80 + (i % 80)];
    if (threadIdx.x < 16) Bs[threadIdx.x] = bias[o0 + threadIdx.x];
    __syncthreads();

    float acc[16];
    #pragma unroll
    for (int i = 0; i < 16; i++) acc[i] = Bs[i];
    const float* sp = speech + (size_t)b * 80 * LSEQ + l;
    for (int c = 0; c < 80; c++) {
        float sv = sp[(size_t)c * LSEQ];
        #pragma unroll
        for (int i = 0; i < 16; i++) acc[i] += Ws[i][c] * sv;
    }
    float* xp = x + ((size_t)b * CEMB + o0) * LSEQ + l;
    #pragma unroll
    for (int i = 0; i < 16; i++) xp[(size_t)i * LSEQ] = acc[i];
}

// ---------------- GroupNorm: x fp32 -> h2 (half2 c-pairs, l PG-permuted) -----
__global__ void group_norm_k(const float* __restrict__ x, const float* __restrict__ w,
                             const float* __restrict__ bb, uint32_t* __restrict__ h2) {
    int bg = blockIdx.x;
    int b = bg >> 5, g = bg & 31;
    const float* xp = x + ((size_t)b * CEMB + g * 32) * LSEQ;
    float s = 0.f, ss = 0.f;
    for (int i = threadIdx.x; i < 32 * LSEQ; i += 512) {
        float v = xp[i];
        s += v; ss += v * v;
    }
    #pragma unroll
    for (int o = 16; o; o >>= 1) {
        s  += __shfl_down_sync(0xffffffffu, s,  o);
        ss += __shfl_down_sync(0xffffffffu, ss, o);
    }
    __shared__ float shs[16], shss[16];
    __shared__ float smean, srstd;
    int wid = threadIdx.x >> 5, lane = threadIdx.x & 31;
    if (!lane) { shs[wid] = s; shss[wid] = ss; }
    __syncthreads();
    if (threadIdx.x == 0) {
        float S = 0.f, SS = 0.f;
        #pragma unroll
        for (int i = 0; i < 16; i++) { S += shs[i]; SS += shss[i]; }
        float mean = S / 32768.f;
        float var  = SS / 32768.f - mean * mean;
        smean = mean;
        srstd = rsqrtf(var + 1e-5f);
    }
    __syncthreads();
    float mean = smean, rstd = srstd;
    uint32_t* hp = h2 + ((size_t)b * KW + g * 16) * LSEQ;
    for (int i = threadIdx.x; i < 16 * LSEQ; i += 512) {
        int cp = i >> 10, l = i & 1023;
        int c = g * 32 + 2 * cp;
        float v0 = (xp[(size_t)(2 * cp) * LSEQ + l] - mean) * rstd * w[c] + bb[c];
        float v1 = (xp[(size_t)(2 * cp + 1) * LSEQ + l] - mean) * rstd * w[c + 1] + bb[c + 1];
        int lw = (l & ~31) | ((l & 7) << 2) | ((l >> 3) & 3);   // PG
        hp[(size_t)cp * LSEQ + lw] = packh2(v0, v1);
    }
}

// ---------------- fp16 MMA GEMM, 3-stage cp.async ----------------------------
#define GEMM_AS_W   5120
#define GEMM_BUF_W  (GEMM_AS_W + 4352)
#define GEMM_SMEM   (GEMM_BUF_W * 3 * 4)

template <bool QKVOUT>
__global__ __launch_bounds__(256, 2) void gemm_wx_mma(
    const uint32_t* __restrict__ W2, const float* __restrict__ bias,
    const uint32_t* __restrict__ X2, const float* __restrict__ res,
    void* __restrict__ Yout, int O)
{
    extern __shared__ uint32_t smbuf[];
    int tid = threadIdx.x, lane = tid & 31, warp = tid >> 5;
    int g = lane >> 2, tg = lane & 3;
    int wm = warp >> 2, wn = warp & 3;
    int b = blockIdx.z, o0 = blockIdx.y << 7, l0 = blockIdx.x << 7;
    const uint32_t* Wp = W2 + (size_t)o0 * KW;
    const uint32_t* Xp = X2 + (size_t)b * KW * LSEQ + l0;
    uint32_t sb = (uint32_t)__cvta_generic_to_shared(smbuf);

    auto prefetch = [&](int kc, int bufi) {
        uint32_t base = sb + (uint32_t)bufi * (GEMM_BUF_W * 4u);
        int k0 = kc << 5;                           // word offset
        #pragma unroll
        for (int j = 0; j < 4; j++) {
            int idx = tid + (j << 8);
            int r = idx >> 3, c = (idx & 7) << 2;
            cpa16(base + (uint32_t)(r * 40 + c) * 4u, Wp + (size_t)r * KW + k0 + c);
        }
        #pragma unroll
        for (int j = 0; j < 4; j++) {
            int idx = tid + (j << 8);
            int r2 = idx >> 5, c2 = (idx & 31) << 2;
            cpa16(base + (uint32_t)(GEMM_AS_W + r2 * 136 + c2) * 4u,
                  Xp + (size_t)(k0 + r2) * LSEQ + c2);
        }
        cpa_commit();
    };

    float acc[4][4][4] = {};
    prefetch(0, 0);
    prefetch(1, 1);
    int use = 0, pre = 2;

    for (int kc = 0; kc < 16; kc++) {
        if (kc < 14) cpa_wait<1>(); else cpa_wait<0>();
        __syncthreads();
        if (kc < 14) prefetch(kc + 2, pre);

        const uint32_t* As = smbuf + use * GEMM_BUF_W;
        const uint32_t* Bs = As + GEMM_AS_W;
        #pragma unroll
        for (int ks = 0; ks < 4; ks++) {
            int kk = ks << 3;
            uint2 aA[4], aB[4];
            #pragma unroll
            for (int mi = 0; mi < 4; mi++) {
                int row = wm * 64 + mi * 16 + g;
                aA[mi] = *(const uint2*)&As[row * 40 + kk + 2 * tg];        // (a0,a2)
                aB[mi] = *(const uint2*)&As[(row + 8) * 40 + kk + 2 * tg];  // (a1,a3)
            }
            uint4 b0 = *(const uint4*)&Bs[(kk + tg) * 136 + wn * 32 + (g << 2)];
            uint4 b1 = *(const uint4*)&Bs[(kk + tg + 4) * 136 + wn * 32 + (g << 2)];
            uint32_t bb0[4] = {b0.x, b0.y, b0.z, b0.w};
            uint32_t bb1[4] = {b1.x, b1.y, b1.z, b1.w};
            #pragma unroll
            for (int mi = 0; mi < 4; mi++)
                #pragma unroll
                for (int ni = 0; ni < 4; ni++)
                    mma_f16(acc[mi][ni], aA[mi].x, aB[mi].x, aA[mi].y, aB[mi].y,
                            bb0[ni], bb1[ni]);
        }
        use = (use == 2) ? 0 : use + 1;
        pre = (pre == 2) ? 0 : pre + 1;
    }

    // epilogue: n order NATURAL -> l = wn*32 + ni*8 + 2*tg (+1)
    #pragma unroll
    for (int mi = 0; mi < 4; mi++) {
        #pragma unroll
        for (int rr = 0; rr < 2; rr++) {
            int o = o0 + wm * 64 + mi * 16 + g + rr * 8;
            float bsv = bias[o];
            #pragma unroll
            for (int ni = 0; ni < 4; ni++) {
                int la = wn * 32 + ni * 8 + (tg << 1);
                float v0 = acc[mi][ni][rr * 2]     + bsv;
                float v1 = acc[mi][ni][rr * 2 + 1] + bsv;
                if (QKVOUT) {
                    // route into per-head Q2[c/2][t] / K2[c/2][s] / V2[c][s/2]
                    uint32_t* Y2 = (uint32_t*)Yout;
                    int hh = o / 192, r = o - hh * 192;
                    size_t headbase = ((size_t)b * 1536 + hh * 96) * LSEQ;  // words
                    int lg = l0 + la;
                    if (r < 128) {
                        __half* hp = (__half*)Y2;
                        size_t hi = 2 * (headbase + (size_t)(r >> 1) * LSEQ + lg) + (r & 1);
                        hp[hi]     = __float2half_rn(v0);
                        hp[hi + 2] = __float2half_rn(v1);
                    } else {
                        int c = r - 128;
                        // V region starts AFTER Q/K (64 word-rows x LSEQ); rows stride KW
                        Y2[headbase + (size_t)64 * LSEQ + (size_t)c * KW + (lg >> 1)]
                            = packh2(v0, v1);
                    }
                } else {
                    float* Y = (float*)Yout;
                    size_t rowoff = ((size_t)b * O + o) * LSEQ + l0 + la;
                    float2 rv = *(const float2*)(res + rowoff);
                    *(float2*)(Y + rowoff) = make_float2(v0 + rv.x, v1 + rv.y);
                }
            }
        }
    }
}

// ---------------- fused flash attention (fp16, double-buffered K/V) ----------
// smem words: Qs[32][136], Ks[2][32][136], Vs[2][64][68], Ps[128][68]
#define FA_QS 0
#define FA_KS 4352                     // two buffers of 4352 words
#define FA_VS 13056                    // two buffers of 4352 words
#define FA_PS 21760
#define FA_SMEM ((21760 + 128 * 68) * 4)

__global__ __launch_bounds__(256, 1) void flash_attn(
    const uint32_t* __restrict__ qkv2, uint32_t* __restrict__ ao2)
{
    extern __shared__ uint32_t sm[];
    uint32_t* Qs = sm + FA_QS;
    uint32_t* Ps = sm + FA_PS;
    uint32_t fb = (uint32_t)__cvta_generic_to_shared(sm);

    int tid = threadIdx.x, lane = tid & 31, warp = tid >> 5;
    int g = lane >> 2, tg = lane & 3;
    int tw = warp << 4;
    int bh = blockIdx.y, b = bh >> 4, hh = bh & 15;
    int t0 = blockIdx.x << 7;
    const uint32_t* Qw = qkv2 + ((size_t)b * 1536 + hh * 96) * LSEQ;
    const uint32_t* Kw = Qw + 32 * LSEQ;
    const uint32_t* Vw = Qw + 64 * LSEQ;       // rows c, stride KW words

    // issue K/V loads for key-tile s0 into buffer p
    auto load_kv = [&](int s0, int p) {
        uint32_t kbase = fb + (uint32_t)(FA_KS + p * 4352) * 4u;
        uint32_t vbase = fb + (uint32_t)(FA_VS + p * 4352) * 4u;
        int snw = s0 >> 1;
        #pragma unroll
        for (int j = 0; j < 4; j++) {
            int idx = tid + (j << 8);
            int r = idx >> 5, c4 = (idx & 31) << 2;           // K: 32 rows x 128 words
            cpa16(kbase + (uint32_t)(r * 136 + c4) * 4u, Kw + (size_t)r * LSEQ + s0 + c4);
            int rv = idx >> 4, cv = (idx & 15) << 2;          // V: 64 rows x 64 words
            cpa16(vbase + (uint32_t)(rv * 68 + cv) * 4u, Vw + (size_t)rv * KW + snw + cv);
        }
        cpa_commit();
    };

    // prologue: Q tile + first K/V tile (buffer 0)
    #pragma unroll
    for (int j = 0; j < 4; j++) {
        int idx = tid + (j << 8);
        int r = idx >> 5, c4 = (idx & 31) << 2;
        cpa16(fb + (uint32_t)(FA_QS + r * 136 + c4) * 4u, Qw + (size_t)r * LSEQ + t0 + c4);
    }
    load_kv(0, 0);

    float accO[8][4] = {};
    float m0 = -1e30f, m1 = -1e30f, l0 = 0.f, l1 = 0.f;

    for (int it = 0; it < 8; it++) {
        int p = it & 1;
        const uint32_t* Ks = sm + FA_KS + p * 4352;
        const uint32_t* Vs = sm + FA_VS + p * 4352;

        cpa_wait<0>();
        __syncthreads();

        // S[16t x 128s] per warp: 4 k-steps over 32 kw
        float accS[16][4] = {};
        #pragma unroll
        for (int kk = 0; kk < 4; kk++) {
            const uint32_t* pq = &Qs[(kk * 8 + tg) * 136 + tw + g];
            uint32_t a0 = pq[0], a1 = pq[8], a2 = pq[4 * 136], a3 = pq[4 * 136 + 8];
            #pragma unroll
            for (int ni = 0; ni < 16; ni++) {
                const uint32_t* q = &Ks[(kk * 8 + tg) * 136 + ni * 8 + g];
                mma_f16(accS[ni], a0, a1, a2, a3, q[0], q[4 * 136]);
            }
        }

        // prefetch next tile into dead buffer, overlapping softmax + PV
        if (it < 7) load_kv((it + 1) << 7, p ^ 1);

        // online softmax: rows t = tw+g (comp 0,1), tw+g+8 (comp 2,3); s natural
        float tm0 = -1e30f, tm1 = -1e30f;
        #pragma unroll
        for (int ni = 0; ni < 16; ni++) {
            #pragma unroll
            for (int v = 0; v < 4; v++) accS[ni][v] *= 0.125f;
            tm0 = fmaxf(tm0, fmaxf(accS[ni][0], accS[ni][1]));
            tm1 = fmaxf(tm1, fmaxf(accS[ni][2], accS[ni][3]));
        }
        tm0 = fmaxf(tm0, __shfl_xor_sync(0xffffffffu, tm0, 1));
        tm0 = fmaxf(tm0, __shfl_xor_sync(0xffffffffu, tm0, 2));
        tm1 = fmaxf(tm1, __shfl_xor_sync(0xffffffffu, tm1, 1));
        tm1 = fmaxf(tm1, __shfl_xor_sync(0xffffffffu, tm1, 2));
        float nm0 = fmaxf(m0, tm0), nm1 = fmaxf(m1, tm1);
        float f0 = __expf(m0 - nm0), f1 = __expf(m1 - nm1);
        float ts0 = 0.f, ts1 = 0.f;
        #pragma unroll
        for (int ni = 0; ni < 16; ni++) {
            float p0 = __expf(accS[ni][0] - nm0);
            float p1 = __expf(accS[ni][1] - nm0);
            float p2 = __expf(accS[ni][2] - nm1);
            float p3 = __expf(accS[ni][3] - nm1);
            ts0 += p0 + p1; ts1 += p2 + p3;
            Ps[(tw + g) * 68 + ni * 4 + tg]     = packh2(p0, p1);   // s pair (ni*8+2tg, +1)
            Ps[(tw + g + 8) * 68 + ni * 4 + tg] = packh2(p2, p3);
        }
        ts0 += __shfl_xor_sync(0xffffffffu, ts0, 1);
        ts0 += __shfl_xor_sync(0xffffffffu, ts0, 2);
        ts1 += __shfl_xor_sync(0xffffffffu, ts1, 1);
        ts1 += __shfl_xor_sync(0xffffffffu, ts1, 2);
        l0 = l0 * f0 + ts0;
        l1 = l1 * f1 + ts1;
        m0 = nm0; m1 = nm1;
        #pragma unroll
        for (int ni = 0; ni < 8; ni++) {
            accO[ni][0] *= f0; accO[ni][1] *= f0;
            accO[ni][2] *= f1; accO[ni][3] *= f1;
        }
        __syncwarp();   // Ps is warp-private: writes above, reads below, same warp

        // O[16t x 64c] += P V^T : 8 k-steps over 64 sw; P and V both s-pair packed
        #pragma unroll
        for (int kk = 0; kk < 8; kk++) {
            int pa = (tw + g) * 68 + kk * 8 + tg;
            uint32_t a0 = Ps[pa], a1 = Ps[pa + 8 * 68], a2 = Ps[pa + 4], a3 = Ps[pa + 8 * 68 + 4];
            #pragma unroll
            for (int ni = 0; ni < 8; ni++) {
                int vb = (ni * 8 + g) * 68 + kk * 8 + tg;
                mma_f16(accO[ni], a0, a1, a2, a3, Vs[vb], Vs[vb + 4]);
            }
        }
        // no end-of-iter barrier: next iter's top barrier orders buffer reuse
    }

    // epilogue: t natural; c pairs adjacent (comp 0/1); store ao2[c/2][PG(t)]
    float inv0 = 1.0f / l0, inv1 = 1.0f / l1;
    int tA = t0 + tw + g;
    int tB = tA + 8;
    int colA = (tA & ~31) | ((tA & 7) << 2) | ((tA >> 3) & 3);
    int colB = (tB & ~31) | ((tB & 7) << 2) | ((tB >> 3) & 3);
    size_t base = ((size_t)b * KW + hh * 32) * LSEQ;
    #pragma unroll
    for (int ni = 0; ni < 8; ni++) {
        int cw = ni * 4 + tg;                  // c pair (ni*8+2tg, +1) -> word row
        ao2[base + (size_t)cw * LSEQ + colA] = packh2(accO[ni][0] * inv0, accO[ni][1] * inv0);
        ao2[base + (size_t)cw * LSEQ + colB] = packh2(accO[ni][2] * inv1, accO[ni][3] * inv1);
    }
}

// ---------------- layer-5 proj GEMV at l=0 only -> d_out ---------------------
// out[b*1024+o] = x[b,o,0] + bias[o] + sum_c W[o,c]*ao[b,c,0]
// Reads fp16 wp2 (PK word-perm) and ao2 (t=0 -> PG col 0); fp32 accumulate.
__global__ void proj_gemv_out(const uint32_t* __restrict__ wp2, const float* __restrict__ bias,
                              const uint32_t* __restrict__ ao2, const float* __restrict__ x,
                              float* __restrict__ out) {
    int wgl = (blockIdx.x << 3) + (threadIdx.x >> 5);   // 0..8191
    int lane = threadIdx.x & 31;
    int b = wgl >> 10, o = wgl & 1023;
    const uint32_t* wrow = wp2 + (size_t)o * KW;
    const uint32_t* arow = ao2 + (size_t)b * KW * LSEQ;
    float acc = 0.f;
    #pragma unroll
    for (int j = 0; j < 16; j++) {
        int kws = lane + (j << 5);
        int kw = (kws & ~7) | ((kws >> 1) & 3) | ((kws & 1) << 2);   // PK inverse
        float2 wv = __half22float2(*(const __half2*)&wrow[kws]);
        float2 av = __half22float2(*(const __half2*)&arow[(size_t)kw * LSEQ]);
        acc += wv.x * av.x + wv.y * av.y;
    }
    #pragma unroll
    for (int off = 16; off; off >>= 1) acc += __shfl_xor_sync(0xffffffffu, acc, off);
    if (!lane) out[wgl] = x[((size_t)b * CEMB + o) * LSEQ] + bias[o] + acc;
}

extern "C" void kernel_launch(void* const* d_in, const int* in_sizes, int n_in,
                              void* d_out, int out_size) {
    const float* speech = (const float*)d_in[0];
    const float* init_w = (const float*)d_in[1];
    const float* init_b = (const float*)d_in[2];
    const float* gn_w   = (const float*)d_in[3];
    const float* gn_b   = (const float*)d_in[4];
    const float* qkv_w  = (const float*)d_in[5];
    const float* qkv_b  = (const float*)d_in[6];
    const float* proj_w = (const float*)d_in[7];
    const float* proj_b = (const float*)d_in[8];

    float *x;
    uint32_t *h2, *qkv2, *ao2, *wq2, *wp2;
    cudaGetSymbolAddress((void**)&x,    g_x);
    cudaGetSymbolAddress((void**)&h2,   g_h2);
    cudaGetSymbolAddress((void**)&qkv2, g_qkv2);
    cudaGetSymbolAddress((void**)&ao2,  g_ao2);
    cudaGetSymbolAddress((void**)&wq2,  g_wq2);
    cudaGetSymbolAddress((void**)&wp2,  g_wp2);

    cudaFuncSetAttribute(flash_attn, cudaFuncAttributeMaxDynamicSharedMemorySize, FA_SMEM);
    cudaFuncSetAttribute(gemm_wx_mma<true>,  cudaFuncAttributeMaxDynamicSharedMemorySize, GEMM_SMEM);
    cudaFuncSetAttribute(gemm_wx_mma<false>, cudaFuncAttributeMaxDynamicSharedMemorySize, GEMM_SMEM);

    pack_w<<<2048, 256>>>(qkv_w,  wq2, 6 * 3 * CEMB * KW);
    pack_w<<<1024, 256>>>(proj_w, wp2, 6 * CEMB * KW);

    init_gemm<<<dim3(LSEQ / 128, CEMB / 16, BB), 128>>>(speech, init_w, init_b, x);

    // layers 0..4: full pipeline
    for (int i = 0; i < 5; i++) {
        group_norm_k<<<BB * NGRP, 512>>>(x, gn_w + (size_t)i * CEMB, gn_b + (size_t)i * CEMB, h2);
        gemm_wx_mma<true><<<dim3(LSEQ / 128, 3 * CEMB / 128, BB), 256, GEMM_SMEM>>>(
            wq2 + (size_t)i * 3 * CEMB * KW, qkv_b + (size_t)i * 3 * CEMB,
            h2, nullptr, qkv2, 3 * CEMB);
        flash_attn<<<dim3(LSEQ / 128, BB * NH), 256, FA_SMEM>>>(qkv2, ao2);
        gemm_wx_mma<false><<<dim3(LSEQ / 128, CEMB / 128, BB), 256, GEMM_SMEM>>>(
            wp2 + (size_t)i * CEMB * KW, proj_b + (size_t)i * CEMB,
            ao2, x, x, CEMB);
    }

    // layer 5: only out[:, :, 0] is ever read -> flash at t-tile 0 only,
    // proj collapses to a GEMV on column 0 fused with residual + output.
    group_norm_k<<<BB * NGRP, 512>>>(x, gn_w + (size_t)5 * CEMB, gn_b + (size_t)5 * CEMB, h2);
    gemm_wx_mma<true><<<dim3(LSEQ / 128, 3 * CEMB / 128, BB), 256, GEMM_SMEM>>>(
        wq2 + (size_t)5 * 3 * CEMB * KW, qkv_b + (size_t)5 * 3 * CEMB,
        h2, nullptr, qkv2, 3 * CEMB);
    flash_attn<<<dim3(1, BB * NH), 256, FA_SMEM>>>(qkv2, ao2);
    proj_gemv_out<<<1024, 256>>>(wp2 + (size_t)5 * CEMB * KW, proj_b + (size_t)5 * CEMB,
                                 ao2, x, (float*)d_out);
}

// round 17
// speedup vs baseline: 2.0767x; 1.0306x over previous
#include <cuda_runtime.h>
#include <cuda_fp16.h>
#include <math.h>
#include <stdint.h>

#define LSEQ 1024
#define CEMB 1024
#define KD   1024
#define KW   512      // k in half2 words
#define BB   8
#define NH   16
#define DH   64
#define NGRP 32

// ---------------- static scratch (device globals; no allocation) -------------
__device__ float    g_x   [(size_t)BB * CEMB * LSEQ];          // natural fp32
__device__ uint32_t g_h2  [(size_t)BB * KW * LSEQ];            // half2[c/2][l PG]
__device__ uint32_t g_qkv2[(size_t)BB * 1536 * LSEQ];          // per head: Q2[32][1024],K2[32][1024],V2[64][512]
__device__ uint32_t g_ao2 [(size_t)BB * KW * LSEQ];            // half2[c/2][t PG]
__device__ uint32_t g_wq2 [(size_t)6 * 3 * CEMB * KW];         // half2, PK word-perm
__device__ uint32_t g_wp2 [(size_t)6 * CEMB * KW];             // half2, PK word-perm

// PK (word idx within 8): stored = (kw&~7)|((kw&3)<<1)|((kw>>2)&1)
// PG (within 32): stored  = (l&~31)|((l&7)<<2)|((l>>3)&3)

// ---------------- helpers ----------------------------------------------------
__device__ __forceinline__ void mma_f16(float (&c)[4],
                                        uint32_t a0, uint32_t a1, uint32_t a2, uint32_t a3,
                                        uint32_t b0, uint32_t b1) {
    asm volatile(
        "mma.sync.aligned.m16n8k16.row.col.f32.f16.f16.f32 "
        "{%0,%1,%2,%3},{%4,%5,%6,%7},{%8,%9},{%0,%1,%2,%3};"
        : "+f"(c[0]), "+f"(c[1]), "+f"(c[2]), "+f"(c[3])
        : "r"(a0), "r"(a1), "r"(a2), "r"(a3), "r"(b0), "r"(b1));
}

__device__ __forceinline__ uint32_t packh2(float a, float b) {
    __half2 h = __floats2half2_rn(a, b);
    return *(uint32_t*)&h;
}

__device__ __forceinline__ void cpa16(uint32_t dst, const void* src) {
    asm volatile("cp.async.cg.shared.global [%0], [%1], 16;" :: "r"(dst), "l"(src));
}
__device__ __forceinline__ void cpa_commit() {
    asm volatile("cp.async.commit_group;" ::);
}
template <int N>
__device__ __forceinline__ void cpa_wait() {
    asm volatile("cp.async.wait_group %0;" :: "n"(N));
}

// ---------------- weight pack: fp32 [o][k] -> half2 words [o][kw PK] ---------
__global__ void pack_w(const float* __restrict__ in, uint32_t* __restrict__ out, int nw) {
    for (int i = blockIdx.x * 256 + threadIdx.x; i < nw; i += gridDim.x * 256) {
        int o = i >> 9, kws = i & (KW - 1);
        int kw = (kws & ~7) | ((kws >> 1) & 3) | ((kws & 1) << 2);   // PK inverse
        const float* p = in + (size_t)o * KD + 2 * kw;
        out[i] = packh2(p[0], p[1]);
    }
}

// ---------------- init projection (x natural fp32) ---------------------------
__global__ void init_gemm(const float* __restrict__ speech, const float* __restrict__ W,
                          const float* __restrict__ bias, float* __restrict__ x) {
    __shared__ float Ws[16][80];
    __shared__ float Bs[16];
    int l  = blockIdx.x * 128 + threadIdx.x;
    int o0 = blockIdx.y * 16;
    int b  = blockIdx.z;
    for (int i = threadIdx.x; i < 16 * 80; i += 128)
        Ws[i / 80][i % 80] = W[(size_t)(o0 + i / 80) * 80 + (i % 80)];
    if (threadIdx.x < 16) Bs[threadIdx.x] = bias[o0 + threadIdx.x];
    __syncthreads();

    float acc[16];
    #pragma unroll
    for (int i = 0; i < 16; i++) acc[i] = Bs[i];
    const float* sp = speech + (size_t)b * 80 * LSEQ + l;
    for (int c = 0; c < 80; c++) {
        float sv = sp[(size_t)c * LSEQ];
        #pragma unroll
        for (int i = 0; i < 16; i++) acc[i] += Ws[i][c] * sv;
    }
    float* xp = x + ((size_t)b * CEMB + o0) * LSEQ + l;
    #pragma unroll
    for (int i = 0; i < 16; i++) xp[(size_t)i * LSEQ] = acc[i];
}

// ---------------- GroupNorm: x fp32 -> h2 (half2 c-pairs, l PG-permuted) -----
__global__ void group_norm_k(const float* __restrict__ x, const float* __restrict__ w,
                             const float* __restrict__ bb, uint32_t* __restrict__ h2) {
    int bg = blockIdx.x;
    int b = bg >> 5, g = bg & 31;
    const float* xp = x + ((size_t)b * CEMB + g * 32) * LSEQ;
    float s = 0.f, ss = 0.f;
    for (int i = threadIdx.x; i < 32 * LSEQ; i += 512) {
        float v = xp[i];
        s += v; ss += v * v;
    }
    #pragma unroll
    for (int o = 16; o; o >>= 1) {
        s  += __shfl_down_sync(0xffffffffu, s,  o);
        ss += __shfl_down_sync(0xffffffffu, ss, o);
    }
    __shared__ float shs[16], shss[16];
    __shared__ float smean, srstd;
    int wid = threadIdx.x >> 5, lane = threadIdx.x & 31;
    if (!lane) { shs[wid] = s; shss[wid] = ss; }
    __syncthreads();
    if (threadIdx.x == 0) {
        float S = 0.f, SS = 0.f;
        #pragma unroll
        for (int i = 0; i < 16; i++) { S += shs[i]; SS += shss[i]; }
        float mean = S / 32768.f;
        float var  = SS / 32768.f - mean * mean;
        smean = mean;
        srstd = rsqrtf(var + 1e-5f);
    }
    __syncthreads();
    float mean = smean, rstd = srstd;
    uint32_t* hp = h2 + ((size_t)b * KW + g * 16) * LSEQ;
    for (int i = threadIdx.x; i < 16 * LSEQ; i += 512) {
        int cp = i >> 10, l = i & 1023;
        int c = g * 32 + 2 * cp;
        float v0 = (xp[(size_t)(2 * cp) * LSEQ + l] - mean) * rstd * w[c] + bb[c];
        float v1 = (xp[(size_t)(2 * cp + 1) * LSEQ + l] - mean) * rstd * w[c + 1] + bb[c + 1];
        int lw = (l & ~31) | ((l & 7) << 2) | ((l >> 3) & 3);   // PG
        hp[(size_t)cp * LSEQ + lw] = packh2(v0, v1);
    }
}

// ---------------- fp16 MMA GEMM, 3-stage cp.async (R14, proven) --------------
#define GEMM_AS_W   5120
#define GEMM_BUF_W  (GEMM_AS_W + 4352)
#define GEMM_SMEM   (GEMM_BUF_W * 3 * 4)

template <bool QKVOUT>
__global__ __launch_bounds__(256, 2) void gemm_wx_mma(
    const uint32_t* __restrict__ W2, const float* __restrict__ bias,
    const uint32_t* __restrict__ X2, const float* __restrict__ res,
    void* __restrict__ Yout, int O)
{
    extern __shared__ uint32_t smbuf[];
    int tid = threadIdx.x, lane = tid & 31, warp = tid >> 5;
    int g = lane >> 2, tg = lane & 3;
    int wm = warp >> 2, wn = warp & 3;
    int b = blockIdx.z, o0 = blockIdx.y << 7, l0 = blockIdx.x << 7;
    const uint32_t* Wp = W2 + (size_t)o0 * KW;
    const uint32_t* Xp = X2 + (size_t)b * KW * LSEQ + l0;
    uint32_t sb = (uint32_t)__cvta_generic_to_shared(smbuf);

    auto prefetch = [&](int kc, int bufi) {
        uint32_t base = sb + (uint32_t)bufi * (GEMM_BUF_W * 4u);
        int k0 = kc << 5;
        #pragma unroll
        for (int j = 0; j < 4; j++) {
            int idx = tid + (j << 8);
            int r = idx >> 3, c = (idx & 7) << 2;
            cpa16(base + (uint32_t)(r * 40 + c) * 4u, Wp + (size_t)r * KW + k0 + c);
        }
        #pragma unroll
        for (int j = 0; j < 4; j++) {
            int idx = tid + (j << 8);
            int r2 = idx >> 5, c2 = (idx & 31) << 2;
            cpa16(base + (uint32_t)(GEMM_AS_W + r2 * 136 + c2) * 4u,
                  Xp + (size_t)(k0 + r2) * LSEQ + c2);
        }
        cpa_commit();
    };

    float acc[4][4][4] = {};
    prefetch(0, 0);
    prefetch(1, 1);
    int use = 0, pre = 2;

    for (int kc = 0; kc < 16; kc++) {
        if (kc < 14) cpa_wait<1>(); else cpa_wait<0>();
        __syncthreads();
        if (kc < 14) prefetch(kc + 2, pre);

        const uint32_t* As = smbuf + use * GEMM_BUF_W;
        const uint32_t* Bs = As + GEMM_AS_W;
        #pragma unroll
        for (int ks = 0; ks < 4; ks++) {
            int kk = ks << 3;
            uint2 aA[4], aB[4];
            #pragma unroll
            for (int mi = 0; mi < 4; mi++) {
                int row = wm * 64 + mi * 16 + g;
                aA[mi] = *(const uint2*)&As[row * 40 + kk + 2 * tg];
                aB[mi] = *(const uint2*)&As[(row + 8) * 40 + kk + 2 * tg];
            }
            uint4 b0 = *(const uint4*)&Bs[(kk + tg) * 136 + wn * 32 + (g << 2)];
            uint4 b1 = *(const uint4*)&Bs[(kk + tg + 4) * 136 + wn * 32 + (g << 2)];
            uint32_t bb0[4] = {b0.x, b0.y, b0.z, b0.w};
            uint32_t bb1[4] = {b1.x, b1.y, b1.z, b1.w};
            #pragma unroll
            for (int mi = 0; mi < 4; mi++)
                #pragma unroll
                for (int ni = 0; ni < 4; ni++)
                    mma_f16(acc[mi][ni], aA[mi].x, aB[mi].x, aA[mi].y, aB[mi].y,
                            bb0[ni], bb1[ni]);
        }
        use = (use == 2) ? 0 : use + 1;
        pre = (pre == 2) ? 0 : pre + 1;
    }

    #pragma unroll
    for (int mi = 0; mi < 4; mi++) {
        #pragma unroll
        for (int rr = 0; rr < 2; rr++) {
            int o = o0 + wm * 64 + mi * 16 + g + rr * 8;
            float bsv = bias[o];
            #pragma unroll
            for (int ni = 0; ni < 4; ni++) {
                int la = wn * 32 + ni * 8 + (tg << 1);
                float v0 = acc[mi][ni][rr * 2]     + bsv;
                float v1 = acc[mi][ni][rr * 2 + 1] + bsv;
                if (QKVOUT) {
                    uint32_t* Y2 = (uint32_t*)Yout;
                    int hh = o / 192, r = o - hh * 192;
                    size_t headbase = ((size_t)b * 1536 + hh * 96) * LSEQ;
                    int lg = l0 + la;
                    if (r < 128) {
                        __half* hp = (__half*)Y2;
                        size_t hi = 2 * (headbase + (size_t)(r >> 1) * LSEQ + lg) + (r & 1);
                        hp[hi]     = __float2half_rn(v0);
                        hp[hi + 2] = __float2half_rn(v1);
                    } else {
                        int c = r - 128;
                        Y2[headbase + (size_t)64 * LSEQ + (size_t)c * KW + (lg >> 1)]
                            = packh2(v0, v1);
                    }
                } else {
                    float* Y = (float*)Yout;
                    size_t rowoff = ((size_t)b * O + o) * LSEQ + l0 + la;
                    float2 rv = *(const float2*)(res + rowoff);
                    *(float2*)(Y + rowoff) = make_float2(v0 + rv.x, v1 + rv.y);
                }
            }
        }
    }
}

// ---------------- fused flash attention: 64-wide key tiles, 2 CTAs/SM --------
// smem words: Qs[32][136]=4352, Ks[2][32][72]=4608, Vs[2][64][36]=4608,
//             Ps[128][36]=4608  -> total 18176 words = 72704 B  (2 CTAs/SM)
#define FA_QS 0
#define FA_KS 4352
#define FA_KB 2304                     // one K buffer: 32 rows x 72
#define FA_VS (FA_KS + 2 * FA_KB)      // 8960
#define FA_VB 2304                     // one V buffer: 64 rows x 36
#define FA_PS (FA_VS + 2 * FA_VB)      // 13568
#define FA_SMEM ((13568 + 128 * 36) * 4)

__global__ __launch_bounds__(256, 2) void flash_attn(
    const uint32_t* __restrict__ qkv2, uint32_t* __restrict__ ao2)
{
    extern __shared__ uint32_t sm[];
    uint32_t* Qs = sm + FA_QS;
    uint32_t* Ps = sm + FA_PS;
    uint32_t fb = (uint32_t)__cvta_generic_to_shared(sm);

    int tid = threadIdx.x, lane = tid & 31, warp = tid >> 5;
    int g = lane >> 2, tg = lane & 3;
    int tw = warp << 4;
    int bh = blockIdx.y, b = bh >> 4, hh = bh & 15;
    int t0 = blockIdx.x << 7;
    const uint32_t* Qw = qkv2 + ((size_t)b * 1536 + hh * 96) * LSEQ;
    const uint32_t* Kw = Qw + 32 * LSEQ;
    const uint32_t* Vw = Qw + 64 * LSEQ;

    // K tile: 32 rows x 64 words (s elems); V tile: 64 rows x 32 words (s pairs)
    auto load_kv = [&](int s0, int p) {
        uint32_t kbase = fb + (uint32_t)(FA_KS + p * FA_KB) * 4u;
        uint32_t vbase = fb + (uint32_t)(FA_VS + p * FA_VB) * 4u;
        int snw = s0 >> 1;
        #pragma unroll
        for (int j = 0; j < 2; j++) {
            int idx = tid + (j << 8);
            int r = idx >> 4, c4 = (idx & 15) << 2;           // K: 32 x 64
            cpa16(kbase + (uint32_t)(r * 72 + c4) * 4u, Kw + (size_t)r * LSEQ + s0 + c4);
            int rv = idx >> 3, cv = (idx & 7) << 2;           // V: 64 x 32
            cpa16(vbase + (uint32_t)(rv * 36 + cv) * 4u, Vw + (size_t)rv * KW + snw + cv);
        }
        cpa_commit();
    };

    // prologue: Q tile + first K/V tile (buffer 0)
    #pragma unroll
    for (int j = 0; j < 4; j++) {
        int idx = tid + (j << 8);
        int r = idx >> 5, c4 = (idx & 31) << 2;
        cpa16(fb + (uint32_t)(FA_QS + r * 136 + c4) * 4u, Qw + (size_t)r * LSEQ + t0 + c4);
    }
    load_kv(0, 0);

    float accO[8][4] = {};
    float m0 = -1e30f, m1 = -1e30f, l0 = 0.f, l1 = 0.f;

    for (int it = 0; it < 16; it++) {
        int p = it & 1;
        const uint32_t* Ks = sm + FA_KS + p * FA_KB;
        const uint32_t* Vs = sm + FA_VS + p * FA_VB;

        cpa_wait<0>();
        __syncthreads();

        // S[16t x 64s] per warp: 4 k-steps over 32 kw, 8 n-tiles
        float accS[8][4] = {};
        #pragma unroll
        for (int kk = 0; kk < 4; kk++) {
            const uint32_t* pq = &Qs[(kk * 8 + tg) * 136 + tw + g];
            uint32_t a0 = pq[0], a1 = pq[8], a2 = pq[4 * 136], a3 = pq[4 * 136 + 8];
            #pragma unroll
            for (int ni = 0; ni < 8; ni++) {
                const uint32_t* q = &Ks[(kk * 8 + tg) * 72 + ni * 8 + g];
                mma_f16(accS[ni], a0, a1, a2, a3, q[0], q[4 * 72]);
            }
        }

        // prefetch next tile into dead buffer, overlapping softmax + PV
        if (it < 15) load_kv((it + 1) << 6, p ^ 1);

        // online softmax: rows t = tw+g (comp 0,1), tw+g+8 (comp 2,3)
        float tm0 = -1e30f, tm1 = -1e30f;
        #pragma unroll
        for (int ni = 0; ni < 8; ni++) {
            #pragma unroll
            for (int v = 0; v < 4; v++) accS[ni][v] *= 0.125f;
            tm0 = fmaxf(tm0, fmaxf(accS[ni][0], accS[ni][1]));
            tm1 = fmaxf(tm1, fmaxf(accS[ni][2], accS[ni][3]));
        }
        tm0 = fmaxf(tm0, __shfl_xor_sync(0xffffffffu, tm0, 1));
        tm0 = fmaxf(tm0, __shfl_xor_sync(0xffffffffu, tm0, 2));
        tm1 = fmaxf(tm1, __shfl_xor_sync(0xffffffffu, tm1, 1));
        tm1 = fmaxf(tm1, __shfl_xor_sync(0xffffffffu, tm1, 2));
        float nm0 = fmaxf(m0, tm0), nm1 = fmaxf(m1, tm1);
        float f0 = __expf(m0 - nm0), f1 = __expf(m1 - nm1);
        float ts0 = 0.f, ts1 = 0.f;
        #pragma unroll
        for (int ni = 0; ni < 8; ni++) {
            float p0 = __expf(accS[ni][0] - nm0);
            float p1 = __expf(accS[ni][1] - nm0);
            float p2 = __expf(accS[ni][2] - nm1);
            float p3 = __expf(accS[ni][3] - nm1);
            ts0 += p0 + p1; ts1 += p2 + p3;
            Ps[(tw + g) * 36 + ni * 4 + tg]     = packh2(p0, p1);   // s pair (ni*8+2tg, +1)
            Ps[(tw + g + 8) * 36 + ni * 4 + tg] = packh2(p2, p3);
        }
        ts0 += __shfl_xor_sync(0xffffffffu, ts0, 1);
        ts0 += __shfl_xor_sync(0xffffffffu, ts0, 2);
        ts1 += __shfl_xor_sync(0xffffffffu, ts1, 1);
        ts1 += __shfl_xor_sync(0xffffffffu, ts1, 2);
        l0 = l0 * f0 + ts0;
        l1 = l1 * f1 + ts1;
        m0 = nm0; m1 = nm1;
        #pragma unroll
        for (int ni = 0; ni < 8; ni++) {
            accO[ni][0] *= f0; accO[ni][1] *= f0;
            accO[ni][2] *= f1; accO[ni][3] *= f1;
        }
        __syncwarp();   // Ps is warp-private

        // O[16t x 64c] += P V^T : 4 k-steps over 32 sw
        #pragma unroll
        for (int kk = 0; kk < 4; kk++) {
            int pa = (tw + g) * 36 + kk * 8 + tg;
            uint32_t a0 = Ps[pa], a1 = Ps[pa + 8 * 36], a2 = Ps[pa + 4], a3 = Ps[pa + 8 * 36 + 4];
            #pragma unroll
            for (int ni = 0; ni < 8; ni++) {
                int vb = (ni * 8 + g) * 36 + kk * 8 + tg;
                mma_f16(accO[ni], a0, a1, a2, a3, Vs[vb], Vs[vb + 4]);
            }
        }
        // no end-of-iter barrier: next iter's top barrier orders buffer reuse
    }

    // epilogue: t natural; c pairs adjacent; store ao2[c/2][PG(t)]
    float inv0 = 1.0f / l0, inv1 = 1.0f / l1;
    int tA = t0 + tw + g;
    int tB = tA + 8;
    int colA = (tA & ~31) | ((tA & 7) << 2) | ((tA >> 3) & 3);
    int colB = (tB & ~31) | ((tB & 7) << 2) | ((tB >> 3) & 3);
    size_t base = ((size_t)b * KW + hh * 32) * LSEQ;
    #pragma unroll
    for (int ni = 0; ni < 8; ni++) {
        int cw = ni * 4 + tg;
        ao2[base + (size_t)cw * LSEQ + colA] = packh2(accO[ni][0] * inv0, accO[ni][1] * inv0);
        ao2[base + (size_t)cw * LSEQ + colB] = packh2(accO[ni][2] * inv1, accO[ni][3] * inv1);
    }
}

// ---------------- layer-5 proj GEMV at l=0 only -> d_out ---------------------
__global__ void proj_gemv_out(const uint32_t* __restrict__ wp2, const float* __restrict__ bias,
                              const uint32_t* __restrict__ ao2, const float* __restrict__ x,
                              float* __restrict__ out) {
    int wgl = (blockIdx.x << 3) + (threadIdx.x >> 5);
    int lane = threadIdx.x & 31;
    int b = wgl >> 10, o = wgl & 1023;
    const uint32_t* wrow = wp2 + (size_t)o * KW;
    const uint32_t* arow = ao2 + (size_t)b * KW * LSEQ;
    float acc = 0.f;
    #pragma unroll
    for (int j = 0; j < 16; j++) {
        int kws = lane + (j << 5);
        int kw = (kws & ~7) | ((kws >> 1) & 3) | ((kws & 1) << 2);
        float2 wv = __half22float2(*(const __half2*)&wrow[kws]);
        float2 av = __half22float2(*(const __half2*)&arow[(size_t)kw * LSEQ]);
        acc += wv.x * av.x + wv.y * av.y;
    }
    #pragma unroll
    for (int off = 16; off; off >>= 1) acc += __shfl_xor_sync(0xffffffffu, acc, off);
    if (!lane) out[wgl] = x[((size_t)b * CEMB + o) * LSEQ] + bias[o] + acc;
}

extern "C" void kernel_launch(void* const* d_in, const int* in_sizes, int n_in,
                              void* d_out, int out_size) {
    const float* speech = (const float*)d_in[0];
    const float* init_w = (const float*)d_in[1];
    const float* init_b = (const float*)d_in[2];
    const float* gn_w   = (const float*)d_in[3];
    const float* gn_b   = (const float*)d_in[4];
    const float* qkv_w  = (const float*)d_in[5];
    const float* qkv_b  = (const float*)d_in[6];
    const float* proj_w = (const float*)d_in[7];
    const float* proj_b = (const float*)d_in[8];

    float *x;
    uint32_t *h2, *qkv2, *ao2, *wq2, *wp2;
    cudaGetSymbolAddress((void**)&x,    g_x);
    cudaGetSymbolAddress((void**)&h2,   g_h2);
    cudaGetSymbolAddress((void**)&qkv2, g_qkv2);
    cudaGetSymbolAddress((void**)&ao2,  g_ao2);
    cudaGetSymbolAddress((void**)&wq2,  g_wq2);
    cudaGetSymbolAddress((void**)&wp2,  g_wp2);

    cudaFuncSetAttribute(flash_attn, cudaFuncAttributeMaxDynamicSharedMemorySize, FA_SMEM);
    cudaFuncSetAttribute(gemm_wx_mma<true>,  cudaFuncAttributeMaxDynamicSharedMemorySize, GEMM_SMEM);
    cudaFuncSetAttribute(gemm_wx_mma<false>, cudaFuncAttributeMaxDynamicSharedMemorySize, GEMM_SMEM);

    pack_w<<<2048, 256>>>(qkv_w,  wq2, 6 * 3 * CEMB * KW);
    pack_w<<<1024, 256>>>(proj_w, wp2, 6 * CEMB * KW);

    init_gemm<<<dim3(LSEQ / 128, CEMB / 16, BB), 128>>>(speech, init_w, init_b, x);

    for (int i = 0; i < 5; i++) {
        group_norm_k<<<BB * NGRP, 512>>>(x, gn_w + (size_t)i * CEMB, gn_b + (size_t)i * CEMB, h2);
        gemm_wx_mma<true><<<dim3(LSEQ / 128, 3 * CEMB / 128, BB), 256, GEMM_SMEM>>>(
            wq2 + (size_t)i * 3 * CEMB * KW, qkv_b + (size_t)i * 3 * CEMB,
            h2, nullptr, qkv2, 3 * CEMB);
        flash_attn<<<dim3(LSEQ / 128, BB * NH), 256, FA_SMEM>>>(qkv2, ao2);
        gemm_wx_mma<false><<<dim3(LSEQ / 128, CEMB / 128, BB), 256, GEMM_SMEM>>>(
            wp2 + (size_t)i * CEMB * KW, proj_b + (size_t)i * CEMB,
            ao2, x, x, CEMB);
    }

    // layer 5: flash at t-tile 0 only; proj collapses to a fused GEMV.
    group_norm_k<<<BB * NGRP, 512>>>(x, gn_w + (size_t)5 * CEMB, gn_b + (size_t)5 * CEMB, h2);
    gemm_wx_mma<true><<<dim3(LSEQ / 128, 3 * CEMB / 128, BB), 256, GEMM_SMEM>>>(
        wq2 + (size_t)5 * 3 * CEMB * KW, qkv_b + (size_t)5 * 3 * CEMB,
        h2, nullptr, qkv2, 3 * CEMB);
    flash_attn<<<dim3(1, BB * NH), 256, FA_SMEM>>>(qkv2, ao2);
    proj_gemv_out<<<1024, 256>>>(wp2 + (size_t)5 * CEMB * KW, proj_b + (size_t)5 * CEMB,
                                 ao2, x, (float*)d_out);
}